// round 1
// baseline (speedup 1.0000x reference)
#include <cuda_runtime.h>
#include <math.h>

// Shapes (fixed by the problem)
#define NB 4
#define NH 16
#define NS 1024
#define ND 1024
#define HD 64
#define NK2 512   // 2 * BUCKETS
#define SPAN 256  // BUCKETS

// ---------------- scratch (device globals; no allocs allowed) ----------------
__device__ float g_re[NK2 * ND];                               // layernormed rel_emb
__device__ float g_q[(size_t)NB * NH * NS * HD];
__device__ float g_k[(size_t)NB * NH * NS * HD];
__device__ float g_v[(size_t)NB * NH * NS * HD];
__device__ float g_posk[NH * NK2 * HD];
__device__ float g_posq[NH * NK2 * HD];
__device__ float g_c2p[(size_t)NB * NH * NS * NK2];
__device__ float g_p2c[(size_t)NB * NH * NS * NK2];
__device__ float g_scores[(size_t)NB * NH * NS * NS];          // also probs (in-place)
__device__ float g_ctx[(size_t)NB * NS * ND];
__device__ int   g_tbl[2 * NS - 1];                            // bucket(delta), delta in [-1023,1023]

// ---------------- bucket table (matches jax f32 semantics) ----------------
__global__ void build_tbl_kernel(int* tbl) {
    int i = blockIdx.x * blockDim.x + threadIdx.x;
    if (i >= 2 * NS - 1) return;
    int rel = i - (NS - 1);
    const float mid = 128.0f;                   // BUCKETS/2
    float signf = (rel > 0) ? 1.0f : (rel < 0 ? -1.0f : 0.0f);
    float abs_pos = (rel < 128 && rel > -128) ? 127.0f : fabsf((float)rel);
    float bucket;
    if (abs_pos <= mid) {
        bucket = (float)rel;
    } else {
        // log((MAX_REL-1)/mid) = log(511/128), rounded to f32 like numpy's double->f32
        const float LOGC = 1.3843393289f;
        float log_pos = ceilf(logf(abs_pos / mid) / LOGC * 127.0f) + mid;
        bucket = log_pos * signf;
    }
    tbl[i] = (int)bucket;
}

// ---------------- LayerNorm over feature dim for rel_emb [512,1024] ----------------
__global__ void ln_kernel(const float* __restrict__ x, const float* __restrict__ g,
                          const float* __restrict__ b, float* __restrict__ y) {
    int row = blockIdx.x;
    const float* xr = x + (size_t)row * ND;
    __shared__ float red[256];
    int tid = threadIdx.x;

    float s = 0.f;
    for (int i = tid; i < ND; i += 256) s += xr[i];
    red[tid] = s; __syncthreads();
    for (int o = 128; o > 0; o >>= 1) { if (tid < o) red[tid] += red[tid + o]; __syncthreads(); }
    float mu = red[0] * (1.0f / ND);
    __syncthreads();

    float v = 0.f;
    for (int i = tid; i < ND; i += 256) { float d = xr[i] - mu; v += d * d; }
    red[tid] = v; __syncthreads();
    for (int o = 128; o > 0; o >>= 1) { if (tid < o) red[tid] += red[tid + o]; __syncthreads(); }
    float var = red[0] * (1.0f / ND);
    float inv = 1.0f / sqrtf(var + 1e-5f);

    for (int i = tid; i < ND; i += 256)
        y[(size_t)row * ND + i] = (xr[i] - mu) * inv * g[i] + b[i];
}

// ---------------- generic SGEMM C = A[M,K] @ B[K,N] + bias, optional head-split out ---------
// splitR == 0: plain row-major [M,N]
// splitR  > 0: out[((bb*16 + h)*splitR + rr)*64 + d] where h=c/64, d=c%64, bb=r/splitR
__global__ void sgemm_bias_kernel(const float* __restrict__ A, const float* __restrict__ Bm,
                                  const float* __restrict__ bias, float* __restrict__ C,
                                  int M, int N, int K, int splitR) {
    __shared__ float As[16][65];
    __shared__ float Bs[16][65];
    const int tid = threadIdx.x;
    const int tx = tid & 15, ty = tid >> 4;
    const int rowBase = blockIdx.y * 64;
    const int colBase = blockIdx.x * 64;
    float acc[4][4] = {};

    for (int k0 = 0; k0 < K; k0 += 16) {
#pragma unroll
        for (int l = 0; l < 4; ++l) {
            int idx = tid + l * 256;
            int r  = idx >> 4, kk = idx & 15;
            As[kk][r] = A[(size_t)(rowBase + r) * K + k0 + kk];
            int kb = idx >> 6, c = idx & 63;
            Bs[kb][c] = Bm[(size_t)(k0 + kb) * N + colBase + c];
        }
        __syncthreads();
#pragma unroll
        for (int kk = 0; kk < 16; ++kk) {
            float a[4], bv[4];
#pragma unroll
            for (int m = 0; m < 4; ++m) a[m] = As[kk][ty * 4 + m];
#pragma unroll
            for (int n = 0; n < 4; ++n) bv[n] = Bs[kk][tx * 4 + n];
#pragma unroll
            for (int m = 0; m < 4; ++m)
#pragma unroll
                for (int n = 0; n < 4; ++n) acc[m][n] += a[m] * bv[n];
        }
        __syncthreads();
    }

#pragma unroll
    for (int m = 0; m < 4; ++m) {
        int r = rowBase + ty * 4 + m;
#pragma unroll
        for (int n = 0; n < 4; ++n) {
            int c = colBase + tx * 4 + n;
            float val = acc[m][n] + bias[c];
            if (splitR == 0) {
                C[(size_t)r * N + c] = val;
            } else {
                int h = c >> 6, d = c & 63;
                int bb = r / splitR, rr = r - bb * splitR;
                C[(((size_t)bb * NH + h) * splitR + rr) * HD + d] = val;
            }
        }
    }
}

// ---------------- batched NT GEMM, K=64: C[batch][i][j] = sum_d A[batch][i][d]*B[bsel][j][d] ---
// mode 0: plain write (c2p / p2c). mode 1: scores epilogue (scale + bias gathers).
__global__ void nt64_kernel(const float* __restrict__ A, const float* __restrict__ Bm,
                            float* __restrict__ C, int N, int bmod, int mode,
                            const float* __restrict__ c2p, const float* __restrict__ p2c,
                            const int* __restrict__ tbl) {
    __shared__ float Asm[64][65];
    __shared__ float Bsm[64][65];
    const int batch = blockIdx.z;
    const float* Ab = A + (size_t)batch * NS * HD;
    const float* Bb = Bm + (size_t)(bmod ? (batch % bmod) : batch) * N * HD;
    const int tid = threadIdx.x;
    const int tx = tid & 15, ty = tid >> 4;
    const int iBase = blockIdx.y * 64;
    const int jBase = blockIdx.x * 64;

#pragma unroll
    for (int l = 0; l < 16; ++l) {
        int idx = tid + l * 256;
        int r = idx >> 6, d = idx & 63;
        Asm[d][r] = Ab[(size_t)(iBase + r) * HD + d];
        Bsm[d][r] = Bb[(size_t)(jBase + r) * HD + d];
    }
    __syncthreads();

    float acc[4][4] = {};
#pragma unroll 16
    for (int d = 0; d < 64; ++d) {
        float a[4], bv[4];
#pragma unroll
        for (int m = 0; m < 4; ++m) a[m] = Asm[d][ty * 4 + m];
#pragma unroll
        for (int n = 0; n < 4; ++n) bv[n] = Bsm[d][tx * 4 + n];
#pragma unroll
        for (int m = 0; m < 4; ++m)
#pragma unroll
            for (int n = 0; n < 4; ++n) acc[m][n] += a[m] * bv[n];
    }

    float* Cb = C + (size_t)batch * NS * N;
    if (mode == 0) {
#pragma unroll
        for (int m = 0; m < 4; ++m) {
            int i = iBase + ty * 4 + m;
#pragma unroll
            for (int n = 0; n < 4; ++n) {
                int j = jBase + tx * 4 + n;
                Cb[(size_t)i * N + j] = acc[m][n];
            }
        }
    } else {
        const float inv192 = 0.07216878364870322f;  // 1/sqrt(64*3)
        const float inv128 = 0.08838834764831845f;  // 1/sqrt(64*2)
        const float* c2pr = c2p + (size_t)batch * NS * NK2;
        const float* p2cr = p2c + (size_t)batch * NS * NK2;
#pragma unroll
        for (int m = 0; m < 4; ++m) {
            int i = iBase + ty * 4 + m;
#pragma unroll
            for (int n = 0; n < 4; ++n) {
                int j = jBase + tx * 4 + n;
                int delta = i - j;
                int t1 = tbl[delta + (NS - 1)];
                int idx1 = min(max(t1 + SPAN, 0), 2 * SPAN - 1);
                int t2 = tbl[(NS - 1) - delta];
                int idx2 = min(max(SPAN - t2, 0), 2 * SPAN - 1);
                float bias = c2pr[(size_t)i * NK2 + idx1] + p2cr[(size_t)j * NK2 + idx2];
                Cb[(size_t)i * N + j] = acc[m][n] * inv192 + bias * inv128;
            }
        }
    }
}

// ---------------- softmax over last dim of scores (in-place), one block per row ----------------
__global__ void softmax_kernel(float* __restrict__ s) {
    size_t row = blockIdx.x;
    float4* p4 = (float4*)(s + row * NS);
    int tid = threadIdx.x;
    float4 x = p4[tid];
    __shared__ float red[256];

    float m = fmaxf(fmaxf(x.x, x.y), fmaxf(x.z, x.w));
    red[tid] = m; __syncthreads();
    for (int o = 128; o > 0; o >>= 1) { if (tid < o) red[tid] = fmaxf(red[tid], red[tid + o]); __syncthreads(); }
    m = red[0]; __syncthreads();

    x.x = expf(x.x - m); x.y = expf(x.y - m); x.z = expf(x.z - m); x.w = expf(x.w - m);
    float sm = x.x + x.y + x.z + x.w;
    red[tid] = sm; __syncthreads();
    for (int o = 128; o > 0; o >>= 1) { if (tid < o) red[tid] += red[tid + o]; __syncthreads(); }
    float inv = 1.0f / red[0];
    x.x *= inv; x.y *= inv; x.z *= inv; x.w *= inv;
    p4[tid] = x;
}

// ---------------- batched PV: ctx[b,i,h*64+d] = sum_j P[batch][i][j] * V[batch][j][d] ----------
__global__ void av_kernel(const float* __restrict__ P, const float* __restrict__ V,
                          float* __restrict__ ctx) {
    __shared__ float Ps[16][65];
    __shared__ float Vs[16][65];
    const int batch = blockIdx.z;
    const int b = batch >> 4, h = batch & 15;
    const float* Pb = P + (size_t)batch * NS * NS;
    const float* Vb = V + (size_t)batch * NS * HD;
    const int tid = threadIdx.x;
    const int tx = tid & 15, ty = tid >> 4;
    const int iBase = blockIdx.y * 64;
    float acc[4][4] = {};

    for (int j0 = 0; j0 < NS; j0 += 16) {
#pragma unroll
        for (int l = 0; l < 4; ++l) {
            int idx = tid + l * 256;
            int r = idx >> 4, jj = idx & 15;
            Ps[jj][r] = Pb[(size_t)(iBase + r) * NS + j0 + jj];
            int jb = idx >> 6, d = idx & 63;
            Vs[jb][d] = Vb[(size_t)(j0 + jb) * HD + d];
        }
        __syncthreads();
#pragma unroll
        for (int jj = 0; jj < 16; ++jj) {
            float a[4], bv[4];
#pragma unroll
            for (int m = 0; m < 4; ++m) a[m] = Ps[jj][ty * 4 + m];
#pragma unroll
            for (int n = 0; n < 4; ++n) bv[n] = Vs[jj][tx * 4 + n];
#pragma unroll
            for (int m = 0; m < 4; ++m)
#pragma unroll
                for (int n = 0; n < 4; ++n) acc[m][n] += a[m] * bv[n];
        }
        __syncthreads();
    }

#pragma unroll
    for (int m = 0; m < 4; ++m) {
        int i = iBase + ty * 4 + m;
#pragma unroll
        for (int n = 0; n < 4; ++n) {
            int d = tx * 4 + n;
            ctx[((size_t)b * NS + i) * ND + h * HD + d] = acc[m][n];
        }
    }
}

// ---------------- launch ----------------
extern "C" void kernel_launch(void* const* d_in, const int* in_sizes, int n_in,
                              void* d_out, int out_size) {
    const float* hs    = (const float*)d_in[0];
    const float* Wq    = (const float*)d_in[1];
    const float* bq    = (const float*)d_in[2];
    const float* Wk    = (const float*)d_in[3];
    const float* bk    = (const float*)d_in[4];
    const float* Wv    = (const float*)d_in[5];
    const float* bv    = (const float*)d_in[6];
    const float* Wo    = (const float*)d_in[7];
    const float* bo    = (const float*)d_in[8];
    const float* rel   = (const float*)d_in[9];
    const float* ln_g  = (const float*)d_in[10];
    const float* ln_b  = (const float*)d_in[11];
    const float* Wpk   = (const float*)d_in[12];
    const float* bpk   = (const float*)d_in[13];
    const float* Wpq   = (const float*)d_in[14];
    const float* bpq   = (const float*)d_in[15];
    float* out = (float*)d_out;

    float *p_re, *p_q, *p_k, *p_v, *p_posk, *p_posq, *p_c2p, *p_p2c, *p_sc, *p_ctx;
    int* p_tbl;
    cudaGetSymbolAddress((void**)&p_re, g_re);
    cudaGetSymbolAddress((void**)&p_q, g_q);
    cudaGetSymbolAddress((void**)&p_k, g_k);
    cudaGetSymbolAddress((void**)&p_v, g_v);
    cudaGetSymbolAddress((void**)&p_posk, g_posk);
    cudaGetSymbolAddress((void**)&p_posq, g_posq);
    cudaGetSymbolAddress((void**)&p_c2p, g_c2p);
    cudaGetSymbolAddress((void**)&p_p2c, g_p2c);
    cudaGetSymbolAddress((void**)&p_sc, g_scores);
    cudaGetSymbolAddress((void**)&p_ctx, g_ctx);
    cudaGetSymbolAddress((void**)&p_tbl, g_tbl);

    build_tbl_kernel<<<9, 256>>>(p_tbl);
    ln_kernel<<<NK2, 256>>>(rel, ln_g, ln_b, p_re);

    // projections -> [B,H,S,hd]
    sgemm_bias_kernel<<<dim3(16, 64), 256>>>(hs, Wq, bq, p_q, NB * NS, ND, ND, NS);
    sgemm_bias_kernel<<<dim3(16, 64), 256>>>(hs, Wk, bk, p_k, NB * NS, ND, ND, NS);
    sgemm_bias_kernel<<<dim3(16, 64), 256>>>(hs, Wv, bv, p_v, NB * NS, ND, ND, NS);

    // positional projections -> [H,2K,hd]
    sgemm_bias_kernel<<<dim3(16, 8), 256>>>(p_re, Wpk, bpk, p_posk, NK2, ND, ND, NK2);
    sgemm_bias_kernel<<<dim3(16, 8), 256>>>(p_re, Wpq, bpq, p_posq, NK2, ND, ND, NK2);

    // c2p[bh][i][kk] = q . pos_k ; p2c[bh][i][kk] = k . pos_q
    nt64_kernel<<<dim3(8, 16, 64), 256>>>(p_q, p_posk, p_c2p, NK2, NH, 0, nullptr, nullptr, nullptr);
    nt64_kernel<<<dim3(8, 16, 64), 256>>>(p_k, p_posq, p_p2c, NK2, NH, 0, nullptr, nullptr, nullptr);

    // scores = qk/sqrt(192) + gathered biases / sqrt(128)
    nt64_kernel<<<dim3(16, 16, 64), 256>>>(p_q, p_k, p_sc, NS, 0, 1, p_c2p, p_p2c, p_tbl);

    softmax_kernel<<<NB * NH * NS, 256>>>(p_sc);

    // ctx = probs @ v -> [B,S,D]
    av_kernel<<<dim3(1, 16, 64), 256>>>(p_sc, p_v, p_ctx);

    // out = ctx @ Wo + bo
    sgemm_bias_kernel<<<dim3(16, 64), 256>>>(p_ctx, Wo, bo, out, NB * NS, ND, ND, 0);
}

// round 3
// speedup vs baseline: 2.0159x; 2.0159x over previous
#include <cuda_runtime.h>
#include <math.h>

// Shapes (fixed by the problem)
#define NB 4
#define NH 16
#define NS 1024
#define ND 1024
#define HD 64
#define NK2 512   // 2 * BUCKETS
#define SPAN 256  // BUCKETS

// ---------------- scratch (device globals; no allocs allowed) ----------------
__device__ float g_re[NK2 * ND];
__device__ float g_q[(size_t)NB * NH * NS * HD];
__device__ float g_k[(size_t)NB * NH * NS * HD];
__device__ float g_v[(size_t)NB * NH * NS * HD];
__device__ float g_posk[NH * NK2 * HD];
__device__ float g_posq[NH * NK2 * HD];
__device__ float g_c2p[(size_t)NB * NH * NS * NK2];
__device__ float g_p2c[(size_t)NB * NH * NS * NK2];
__device__ float g_scores[(size_t)NB * NH * NS * NS];
__device__ float g_ctx[(size_t)NB * NS * ND];
__device__ int   g_tbl[2 * NS - 1];

// ---------------- helpers ----------------
__device__ __forceinline__ float f2tf(float x) {
    unsigned u;
    asm("cvt.rna.tf32.f32 %0, %1;" : "=r"(u) : "f"(x));
    return __uint_as_float(u);
}

__device__ __forceinline__ void mma_tf32(float* c, const float* a, const float* b) {
    asm volatile("mma.sync.aligned.m16n8k8.row.col.f32.tf32.tf32.f32 "
                 "{%0,%1,%2,%3}, {%4,%5,%6,%7}, {%8,%9}, {%0,%1,%2,%3};\n"
                 : "+f"(c[0]), "+f"(c[1]), "+f"(c[2]), "+f"(c[3])
                 : "r"(__float_as_uint(a[0])), "r"(__float_as_uint(a[1])),
                   "r"(__float_as_uint(a[2])), "r"(__float_as_uint(a[3])),
                   "r"(__float_as_uint(b[0])), "r"(__float_as_uint(b[1])));
}

__device__ __forceinline__ float4 cvt4(float4 v) {
    v.x = f2tf(v.x); v.y = f2tf(v.y); v.z = f2tf(v.z); v.w = f2tf(v.w);
    return v;
}

// ---------------- bucket table ----------------
__global__ void build_tbl_kernel(int* tbl) {
    int i = blockIdx.x * blockDim.x + threadIdx.x;
    if (i >= 2 * NS - 1) return;
    int rel = i - (NS - 1);
    const float mid = 128.0f;
    float signf = (rel > 0) ? 1.0f : (rel < 0 ? -1.0f : 0.0f);
    float abs_pos = (rel < 128 && rel > -128) ? 127.0f : fabsf((float)rel);
    float bucket;
    if (abs_pos <= mid) {
        bucket = (float)rel;
    } else {
        const float LOGC = 1.3843393289f;  // log(511/128) as f32
        float log_pos = ceilf(logf(abs_pos / mid) / LOGC * 127.0f) + mid;
        bucket = log_pos * signf;
    }
    tbl[i] = (int)bucket;
}

// ---------------- LayerNorm for rel_emb [512,1024] ----------------
__global__ void ln_kernel(const float* __restrict__ x, const float* __restrict__ g,
                          const float* __restrict__ b, float* __restrict__ y) {
    int row = blockIdx.x;
    const float* xr = x + (size_t)row * ND;
    __shared__ float red[256];
    int tid = threadIdx.x;

    float s = 0.f;
    for (int i = tid; i < ND; i += 256) s += xr[i];
    red[tid] = s; __syncthreads();
    for (int o = 128; o > 0; o >>= 1) { if (tid < o) red[tid] += red[tid + o]; __syncthreads(); }
    float mu = red[0] * (1.0f / ND);
    __syncthreads();

    float v = 0.f;
    for (int i = tid; i < ND; i += 256) { float d = xr[i] - mu; v += d * d; }
    red[tid] = v; __syncthreads();
    for (int o = 128; o > 0; o >>= 1) { if (tid < o) red[tid] += red[tid + o]; __syncthreads(); }
    float var = red[0] * (1.0f / ND);
    float inv = 1.0f / sqrtf(var + 1e-5f);

    for (int i = tid; i < ND; i += 256)
        y[(size_t)row * ND + i] = (xr[i] - mu) * inv * g[i] + b[i];
}

// ============================================================================
// mm_bias_tf32: C[M,N] = A[M,K] @ B[K,N] + bias   (tf32 tensor core)
// Block tile 128x128, K-chunk 32, 256 threads / 8 warps (4x2), warp tile 32x64.
// splitR == 0: plain row-major; else head-split store.
// ============================================================================
__global__ __launch_bounds__(256) void mm_bias_tf32(
    const float* __restrict__ A, const float* __restrict__ B,
    const float* __restrict__ bias, float* __restrict__ C,
    int M, int N, int K, int splitR)
{
    __shared__ float As[128][36];   // [m][k]
    __shared__ float Bs[32][136];   // [k][n]

    const int t = threadIdx.x, l = t & 31, w = t >> 5;
    const int gm = l >> 2, kq = l & 3;
    const int warpM = (w >> 1) * 32, warpN = (w & 1) * 64;
    const int rowBase = blockIdx.y * 128, colBase = blockIdx.x * 128;

    float acc[2][8][4];
#pragma unroll
    for (int i = 0; i < 2; ++i)
#pragma unroll
        for (int j = 0; j < 8; ++j)
#pragma unroll
            for (int e = 0; e < 4; ++e) acc[i][j][e] = 0.f;

    const int ar = t >> 1, ac = (t & 1) * 16;   // A stage: row, col-base
    const int bk = t >> 3, bc = (t & 7) * 4;    // B stage: k-row, col-base

    float4 aG[4], bG[4];
#pragma unroll
    for (int i = 0; i < 4; ++i)
        aG[i] = *(const float4*)(A + (size_t)(rowBase + ar) * K + ac + i * 4);
#pragma unroll
    for (int i = 0; i < 4; ++i)
        bG[i] = *(const float4*)(B + (size_t)bk * N + colBase + bc + i * 32);

    for (int k0 = 0; k0 < K; k0 += 32) {
#pragma unroll
        for (int i = 0; i < 4; ++i)
            *(float4*)&As[ar][ac + i * 4] = cvt4(aG[i]);
#pragma unroll
        for (int i = 0; i < 4; ++i)
            *(float4*)&Bs[bk][bc + i * 32] = cvt4(bG[i]);
        __syncthreads();

        if (k0 + 32 < K) {
#pragma unroll
            for (int i = 0; i < 4; ++i)
                aG[i] = *(const float4*)(A + (size_t)(rowBase + ar) * K + k0 + 32 + ac + i * 4);
#pragma unroll
            for (int i = 0; i < 4; ++i)
                bG[i] = *(const float4*)(B + (size_t)(k0 + 32 + bk) * N + colBase + bc + i * 32);
        }

#pragma unroll
        for (int ks = 0; ks < 4; ++ks) {
            const int k = ks * 8;
            float a[2][4], b[8][2];
#pragma unroll
            for (int mt = 0; mt < 2; ++mt) {
                int m = warpM + mt * 16 + gm;
                a[mt][0] = As[m][k + kq];
                a[mt][1] = As[m + 8][k + kq];
                a[mt][2] = As[m][k + kq + 4];
                a[mt][3] = As[m + 8][k + kq + 4];
            }
#pragma unroll
            for (int nt = 0; nt < 8; ++nt) {
                int n = warpN + nt * 8 + gm;
                b[nt][0] = Bs[k + kq][n];
                b[nt][1] = Bs[k + kq + 4][n];
            }
#pragma unroll
            for (int mt = 0; mt < 2; ++mt)
#pragma unroll
                for (int nt = 0; nt < 8; ++nt)
                    mma_tf32(acc[mt][nt], a[mt], b[nt]);
        }
        __syncthreads();
    }

#pragma unroll
    for (int mt = 0; mt < 2; ++mt) {
#pragma unroll
        for (int nt = 0; nt < 8; ++nt) {
            int r0 = rowBase + warpM + mt * 16 + gm;
            int c0 = colBase + warpN + nt * 8 + kq * 2;
#pragma unroll
            for (int e = 0; e < 4; ++e) {
                int r = r0 + (e >> 1) * 8;
                int c = c0 + (e & 1);
                float val = acc[mt][nt][e] + bias[c];
                if (splitR == 0) {
                    C[(size_t)r * N + c] = val;
                } else {
                    int h = c >> 6, d = c & 63;
                    int bb = r / splitR, rr = r - bb * splitR;
                    C[(((size_t)bb * NH + h) * splitR + rr) * HD + d] = val;
                }
            }
        }
    }
}

// ============================================================================
// nt64_tf32: batched C[z][i][j] = sum_d A[z][i][d] * B[zB][j][d]   (K=64, NT)
// Block 128x128. mode 0: plain write. mode 1: scores epilogue (scale+gather).
// ============================================================================
__global__ __launch_bounds__(256) void nt64_tf32(
    const float* __restrict__ A, const float* __restrict__ Bm,
    float* __restrict__ C, int N, int bmod, int mode,
    const float* __restrict__ c2p, const float* __restrict__ p2c,
    const int* __restrict__ tbl)
{
    __shared__ float As[128][36];   // [i][d]
    __shared__ float Bs[128][36];   // [j][d]

    const int t = threadIdx.x, l = t & 31, w = t >> 5;
    const int gm = l >> 2, kq = l & 3;
    const int warpM = (w >> 1) * 32, warpN = (w & 1) * 64;
    const int batch = blockIdx.z;
    const int iBase = blockIdx.y * 128, jBase = blockIdx.x * 128;

    const float* Ab = A + (size_t)batch * NS * HD;
    const float* Bb = Bm + (size_t)(bmod ? (batch % bmod) : batch) * N * HD;

    float acc[2][8][4];
#pragma unroll
    for (int i = 0; i < 2; ++i)
#pragma unroll
        for (int j = 0; j < 8; ++j)
#pragma unroll
            for (int e = 0; e < 4; ++e) acc[i][j][e] = 0.f;

    const int sr = t >> 1, sc = (t & 1) * 16;

    float4 aG[4], bG[4];
#pragma unroll
    for (int i = 0; i < 4; ++i) {
        aG[i] = *(const float4*)(Ab + (size_t)(iBase + sr) * HD + sc + i * 4);
        bG[i] = *(const float4*)(Bb + (size_t)(jBase + sr) * HD + sc + i * 4);
    }

#pragma unroll
    for (int ck = 0; ck < 2; ++ck) {
#pragma unroll
        for (int i = 0; i < 4; ++i) {
            *(float4*)&As[sr][sc + i * 4] = cvt4(aG[i]);
            *(float4*)&Bs[sr][sc + i * 4] = cvt4(bG[i]);
        }
        __syncthreads();

        if (ck == 0) {
#pragma unroll
            for (int i = 0; i < 4; ++i) {
                aG[i] = *(const float4*)(Ab + (size_t)(iBase + sr) * HD + 32 + sc + i * 4);
                bG[i] = *(const float4*)(Bb + (size_t)(jBase + sr) * HD + 32 + sc + i * 4);
            }
        }

#pragma unroll
        for (int ks = 0; ks < 4; ++ks) {
            const int k = ks * 8;
            float a[2][4], b[8][2];
#pragma unroll
            for (int mt = 0; mt < 2; ++mt) {
                int m = warpM + mt * 16 + gm;
                a[mt][0] = As[m][k + kq];
                a[mt][1] = As[m + 8][k + kq];
                a[mt][2] = As[m][k + kq + 4];
                a[mt][3] = As[m + 8][k + kq + 4];
            }
#pragma unroll
            for (int nt = 0; nt < 8; ++nt) {
                int n = warpN + nt * 8 + gm;
                b[nt][0] = Bs[n][k + kq];
                b[nt][1] = Bs[n][k + kq + 4];
            }
#pragma unroll
            for (int mt = 0; mt < 2; ++mt)
#pragma unroll
                for (int nt = 0; nt < 8; ++nt)
                    mma_tf32(acc[mt][nt], a[mt], b[nt]);
        }
        __syncthreads();
    }

    float* Cb = C + (size_t)batch * NS * N;
    if (mode == 0) {
#pragma unroll
        for (int mt = 0; mt < 2; ++mt)
#pragma unroll
            for (int nt = 0; nt < 8; ++nt) {
                int r0 = iBase + warpM + mt * 16 + gm;
                int c0 = jBase + warpN + nt * 8 + kq * 2;
#pragma unroll
                for (int e = 0; e < 4; ++e)
                    Cb[(size_t)(r0 + (e >> 1) * 8) * N + c0 + (e & 1)] = acc[mt][nt][e];
            }
    } else {
        const float inv192 = 0.07216878364870322f;  // 1/sqrt(64*3)
        const float inv128 = 0.08838834764831845f;  // 1/sqrt(64*2)
        const float* c2pr = c2p + (size_t)batch * NS * NK2;
        const float* p2cr = p2c + (size_t)batch * NS * NK2;
#pragma unroll
        for (int mt = 0; mt < 2; ++mt)
#pragma unroll
            for (int nt = 0; nt < 8; ++nt) {
                int r0 = iBase + warpM + mt * 16 + gm;
                int c0 = jBase + warpN + nt * 8 + kq * 2;
#pragma unroll
                for (int e = 0; e < 4; ++e) {
                    int i = r0 + (e >> 1) * 8;
                    int j = c0 + (e & 1);
                    int delta = i - j;
                    int t1 = tbl[delta + (NS - 1)];
                    int idx1 = min(max(t1 + SPAN, 0), 2 * SPAN - 1);
                    int t2 = tbl[(NS - 1) - delta];
                    int idx2 = min(max(SPAN - t2, 0), 2 * SPAN - 1);
                    float bias = c2pr[(size_t)i * NK2 + idx1] + p2cr[(size_t)j * NK2 + idx2];
                    Cb[(size_t)i * N + j] = acc[mt][nt][e] * inv192 + bias * inv128;
                }
            }
    }
}

// ============================================================================
// av_tf32: batched ctx[b,i,h*64+d] = sum_j P[z][i][j] * V[z][j][d]
// Block 128 rows x 64 cols. 8 warps (4x2), warp tile 32x32.
// ============================================================================
__global__ __launch_bounds__(256) void av_tf32(
    const float* __restrict__ P, const float* __restrict__ V,
    float* __restrict__ ctx)
{
    __shared__ float As[128][36];  // P tile [i][k]
    __shared__ float Bs[32][72];   // V tile [k][n]

    const int t = threadIdx.x, l = t & 31, w = t >> 5;
    const int gm = l >> 2, kq = l & 3;
    const int warpM = (w >> 1) * 32, warpN = (w & 1) * 32;
    const int batch = blockIdx.y;
    const int bz = batch >> 4, h = batch & 15;
    const int rowBase = blockIdx.x * 128;

    const float* Pb = P + (size_t)batch * NS * NS;
    const float* Vb = V + (size_t)batch * NS * HD;

    float acc[2][4][4];
#pragma unroll
    for (int i = 0; i < 2; ++i)
#pragma unroll
        for (int j = 0; j < 4; ++j)
#pragma unroll
            for (int e = 0; e < 4; ++e) acc[i][j][e] = 0.f;

    const int ar = t >> 1, ac = (t & 1) * 16;
    const int bk = t >> 3, bc = (t & 7) * 4;

    float4 aG[4], bG[2];
#pragma unroll
    for (int i = 0; i < 4; ++i)
        aG[i] = *(const float4*)(Pb + (size_t)(rowBase + ar) * NS + ac + i * 4);
#pragma unroll
    for (int i = 0; i < 2; ++i)
        bG[i] = *(const float4*)(Vb + (size_t)bk * HD + bc + i * 32);

    for (int k0 = 0; k0 < NS; k0 += 32) {
#pragma unroll
        for (int i = 0; i < 4; ++i)
            *(float4*)&As[ar][ac + i * 4] = cvt4(aG[i]);
#pragma unroll
        for (int i = 0; i < 2; ++i)
            *(float4*)&Bs[bk][bc + i * 32] = cvt4(bG[i]);
        __syncthreads();

        if (k0 + 32 < NS) {
#pragma unroll
            for (int i = 0; i < 4; ++i)
                aG[i] = *(const float4*)(Pb + (size_t)(rowBase + ar) * NS + k0 + 32 + ac + i * 4);
#pragma unroll
            for (int i = 0; i < 2; ++i)
                bG[i] = *(const float4*)(Vb + (size_t)(k0 + 32 + bk) * HD + bc + i * 32);
        }

#pragma unroll
        for (int ks = 0; ks < 4; ++ks) {
            const int k = ks * 8;
            float a[2][4], b[4][2];
#pragma unroll
            for (int mt = 0; mt < 2; ++mt) {
                int m = warpM + mt * 16 + gm;
                a[mt][0] = As[m][k + kq];
                a[mt][1] = As[m + 8][k + kq];
                a[mt][2] = As[m][k + kq + 4];
                a[mt][3] = As[m + 8][k + kq + 4];
            }
#pragma unroll
            for (int nt = 0; nt < 4; ++nt) {
                int n = warpN + nt * 8 + gm;
                b[nt][0] = Bs[k + kq][n];
                b[nt][1] = Bs[k + kq + 4][n];
            }
#pragma unroll
            for (int mt = 0; mt < 2; ++mt)
#pragma unroll
                for (int nt = 0; nt < 4; ++nt)
                    mma_tf32(acc[mt][nt], a[mt], b[nt]);
        }
        __syncthreads();
    }

#pragma unroll
    for (int mt = 0; mt < 2; ++mt)
#pragma unroll
        for (int nt = 0; nt < 4; ++nt) {
            int r0 = rowBase + warpM + mt * 16 + gm;
            int c0 = warpN + nt * 8 + kq * 2;
#pragma unroll
            for (int e = 0; e < 4; ++e) {
                int i = r0 + (e >> 1) * 8;
                int d = c0 + (e & 1);
                ctx[((size_t)bz * NS + i) * ND + h * HD + d] = acc[mt][nt][e];
            }
        }
}

// ---------------- softmax (in-place), one block per row ----------------
__global__ void softmax_kernel(float* __restrict__ s) {
    size_t row = blockIdx.x;
    float4* p4 = (float4*)(s + row * NS);
    int tid = threadIdx.x;
    float4 x = p4[tid];
    __shared__ float red[256];

    float m = fmaxf(fmaxf(x.x, x.y), fmaxf(x.z, x.w));
    red[tid] = m; __syncthreads();
    for (int o = 128; o > 0; o >>= 1) { if (tid < o) red[tid] = fmaxf(red[tid], red[tid + o]); __syncthreads(); }
    m = red[0]; __syncthreads();

    x.x = expf(x.x - m); x.y = expf(x.y - m); x.z = expf(x.z - m); x.w = expf(x.w - m);
    float sm = x.x + x.y + x.z + x.w;
    red[tid] = sm; __syncthreads();
    for (int o = 128; o > 0; o >>= 1) { if (tid < o) red[tid] += red[tid + o]; __syncthreads(); }
    float inv = 1.0f / red[0];
    x.x *= inv; x.y *= inv; x.z *= inv; x.w *= inv;
    p4[tid] = x;
}

// ---------------- launch ----------------
extern "C" void kernel_launch(void* const* d_in, const int* in_sizes, int n_in,
                              void* d_out, int out_size) {
    const float* hs    = (const float*)d_in[0];
    const float* Wq    = (const float*)d_in[1];
    const float* bq    = (const float*)d_in[2];
    const float* Wk    = (const float*)d_in[3];
    const float* bk    = (const float*)d_in[4];
    const float* Wv    = (const float*)d_in[5];
    const float* bv    = (const float*)d_in[6];
    const float* Wo    = (const float*)d_in[7];
    const float* bo    = (const float*)d_in[8];
    const float* rel   = (const float*)d_in[9];
    const float* ln_g  = (const float*)d_in[10];
    const float* ln_b  = (const float*)d_in[11];
    const float* Wpk   = (const float*)d_in[12];
    const float* bpk   = (const float*)d_in[13];
    const float* Wpq   = (const float*)d_in[14];
    const float* bpq   = (const float*)d_in[15];
    float* out = (float*)d_out;

    float *p_re, *p_q, *p_k, *p_v, *p_posk, *p_posq, *p_c2p, *p_p2c, *p_sc, *p_ctx;
    int* p_tbl;
    cudaGetSymbolAddress((void**)&p_re, g_re);
    cudaGetSymbolAddress((void**)&p_q, g_q);
    cudaGetSymbolAddress((void**)&p_k, g_k);
    cudaGetSymbolAddress((void**)&p_v, g_v);
    cudaGetSymbolAddress((void**)&p_posk, g_posk);
    cudaGetSymbolAddress((void**)&p_posq, g_posq);
    cudaGetSymbolAddress((void**)&p_c2p, g_c2p);
    cudaGetSymbolAddress((void**)&p_p2c, g_p2c);
    cudaGetSymbolAddress((void**)&p_sc, g_scores);
    cudaGetSymbolAddress((void**)&p_ctx, g_ctx);
    cudaGetSymbolAddress((void**)&p_tbl, g_tbl);

    build_tbl_kernel<<<9, 256>>>(p_tbl);
    ln_kernel<<<NK2, 256>>>(rel, ln_g, ln_b, p_re);

    // projections -> [B,H,S,hd]
    mm_bias_tf32<<<dim3(8, 32), 256>>>(hs, Wq, bq, p_q, NB * NS, ND, ND, NS);
    mm_bias_tf32<<<dim3(8, 32), 256>>>(hs, Wk, bk, p_k, NB * NS, ND, ND, NS);
    mm_bias_tf32<<<dim3(8, 32), 256>>>(hs, Wv, bv, p_v, NB * NS, ND, ND, NS);

    // positional projections -> [H,2K,hd]
    mm_bias_tf32<<<dim3(8, 4), 256>>>(p_re, Wpk, bpk, p_posk, NK2, ND, ND, NK2);
    mm_bias_tf32<<<dim3(8, 4), 256>>>(p_re, Wpq, bpq, p_posq, NK2, ND, ND, NK2);

    // c2p / p2c
    nt64_tf32<<<dim3(4, 8, 64), 256>>>(p_q, p_posk, p_c2p, NK2, NH, 0, nullptr, nullptr, nullptr);
    nt64_tf32<<<dim3(4, 8, 64), 256>>>(p_k, p_posq, p_p2c, NK2, NH, 0, nullptr, nullptr, nullptr);

    // scores = qk/sqrt(192) + gathered biases / sqrt(128)
    nt64_tf32<<<dim3(8, 8, 64), 256>>>(p_q, p_k, p_sc, NS, 0, 1, p_c2p, p_p2c, p_tbl);

    softmax_kernel<<<NB * NH * NS, 256>>>(p_sc);

    // ctx = probs @ v
    av_tf32<<<dim3(8, 64), 256>>>(p_sc, p_v, p_ctx);

    // out = ctx @ Wo + bo
    mm_bias_tf32<<<dim3(8, 32), 256>>>(p_ctx, Wo, bo, out, NB * NS, ND, ND, 0);
}

// round 4
// speedup vs baseline: 2.4316x; 1.2062x over previous
#include <cuda_runtime.h>
#include <math.h>

// Shapes (fixed by the problem)
#define NB 4
#define NH 16
#define NS 1024
#define ND 1024
#define HD 64
#define NK2 512   // 2 * BUCKETS
#define SPAN 256  // BUCKETS

// ---------------- scratch (device globals; no allocs allowed) ----------------
__device__ float g_re[NK2 * ND];
__device__ float g_q[(size_t)NB * NH * NS * HD];
__device__ float g_k[(size_t)NB * NH * NS * HD];
__device__ float g_v[(size_t)NB * NH * NS * HD];
__device__ float g_posk[NH * NK2 * HD];
__device__ float g_posq[NH * NK2 * HD];
__device__ float g_c2p[(size_t)NB * NH * NS * NK2];
__device__ float g_p2c[(size_t)NB * NH * NS * NK2];
__device__ float g_scores[(size_t)NB * NH * NS * NS];
__device__ float g_ctx[(size_t)NB * NS * ND];
__device__ int   g_tbl[2 * NS - 1];

// ---------------- helpers ----------------
__device__ __forceinline__ float f2tf(float x) {
    unsigned u;
    asm("cvt.rna.tf32.f32 %0, %1;" : "=r"(u) : "f"(x));
    return __uint_as_float(u);
}

__device__ __forceinline__ void mma_tf32(float* c, const float* a, const float* b) {
    asm volatile("mma.sync.aligned.m16n8k8.row.col.f32.tf32.tf32.f32 "
                 "{%0,%1,%2,%3}, {%4,%5,%6,%7}, {%8,%9}, {%0,%1,%2,%3};\n"
                 : "+f"(c[0]), "+f"(c[1]), "+f"(c[2]), "+f"(c[3])
                 : "r"(__float_as_uint(a[0])), "r"(__float_as_uint(a[1])),
                   "r"(__float_as_uint(a[2])), "r"(__float_as_uint(a[3])),
                   "r"(__float_as_uint(b[0])), "r"(__float_as_uint(b[1])));
}

__device__ __forceinline__ void cp16(float* dst, const float* src) {
    unsigned s = (unsigned)__cvta_generic_to_shared(dst);
    asm volatile("cp.async.cg.shared.global [%0], [%1], 16;" :: "r"(s), "l"(src));
}
__device__ __forceinline__ void cp_commit() { asm volatile("cp.async.commit_group;"); }
__device__ __forceinline__ void cp_wait0()  { asm volatile("cp.async.wait_group 0;"); }

// ---------------- bucket table ----------------
__global__ void build_tbl_kernel(int* tbl) {
    int i = blockIdx.x * blockDim.x + threadIdx.x;
    if (i >= 2 * NS - 1) return;
    int rel = i - (NS - 1);
    const float mid = 128.0f;
    float signf = (rel > 0) ? 1.0f : (rel < 0 ? -1.0f : 0.0f);
    float abs_pos = (rel < 128 && rel > -128) ? 127.0f : fabsf((float)rel);
    float bucket;
    if (abs_pos <= mid) {
        bucket = (float)rel;
    } else {
        const float LOGC = 1.3843393289f;  // log(511/128) as f32
        float log_pos = ceilf(logf(abs_pos / mid) / LOGC * 127.0f) + mid;
        bucket = log_pos * signf;
    }
    tbl[i] = (int)bucket;
}

// ---------------- LayerNorm for rel_emb [512,1024] ----------------
__global__ void ln_kernel(const float* __restrict__ x, const float* __restrict__ g,
                          const float* __restrict__ b, float* __restrict__ y) {
    int row = blockIdx.x;
    const float* xr = x + (size_t)row * ND;
    __shared__ float red[256];
    int tid = threadIdx.x;

    float s = 0.f;
    for (int i = tid; i < ND; i += 256) s += xr[i];
    red[tid] = s; __syncthreads();
    for (int o = 128; o > 0; o >>= 1) { if (tid < o) red[tid] += red[tid + o]; __syncthreads(); }
    float mu = red[0] * (1.0f / ND);
    __syncthreads();

    float v = 0.f;
    for (int i = tid; i < ND; i += 256) { float d = xr[i] - mu; v += d * d; }
    red[tid] = v; __syncthreads();
    for (int o = 128; o > 0; o >>= 1) { if (tid < o) red[tid] += red[tid + o]; __syncthreads(); }
    float var = red[0] * (1.0f / ND);
    float inv = 1.0f / sqrtf(var + 1e-5f);

    for (int i = tid; i < ND; i += 256)
        y[(size_t)row * ND + i] = (xr[i] - mu) * inv * g[i] + b[i];
}

// ============================================================================
// mm_bias_tf32: C[M,N] = A[M,K] @ B[K,N] + bias   (tf32 tensor core)
// 128x128 block tile, K-chunk 32, cp.async staging, 2 CTAs/SM.
// Fragments are cvt.rna'd at load (raw fp32 inputs).
// splitR == 0: plain row-major store; else head-split store (+tf32 round).
// ============================================================================
__global__ __launch_bounds__(256, 2) void mm_bias_tf32(
    const float* __restrict__ A, const float* __restrict__ B,
    const float* __restrict__ bias, float* __restrict__ C,
    int M, int N, int K, int splitR)
{
    __shared__ float As[128][36];   // [m][k]  (4m+k)%32 conflict-free
    __shared__ float Bs[32][136];   // [k][n]  (8k+n)%32 conflict-free

    const int t = threadIdx.x, l = t & 31, w = t >> 5;
    const int gm = l >> 2, kq = l & 3;
    const int warpM = (w >> 1) * 32, warpN = (w & 1) * 64;
    const int rowBase = blockIdx.y * 128, colBase = blockIdx.x * 128;

    float acc[2][8][4];
#pragma unroll
    for (int i = 0; i < 2; ++i)
#pragma unroll
        for (int j = 0; j < 8; ++j)
#pragma unroll
            for (int e = 0; e < 4; ++e) acc[i][j][e] = 0.f;

    const int ar = t >> 1, ac = (t & 1) * 16;   // A stage: row, col-base
    const int bk = t >> 3, bc = (t & 7) * 4;    // B stage: k-row, col-base

    for (int k0 = 0; k0 < K; k0 += 32) {
#pragma unroll
        for (int i = 0; i < 4; ++i)
            cp16(&As[ar][ac + i * 4], A + (size_t)(rowBase + ar) * K + k0 + ac + i * 4);
#pragma unroll
        for (int i = 0; i < 4; ++i)
            cp16(&Bs[bk][bc + i * 32], B + (size_t)(k0 + bk) * N + colBase + bc + i * 32);
        cp_commit();
        cp_wait0();
        __syncthreads();

#pragma unroll
        for (int ks = 0; ks < 4; ++ks) {
            const int k = ks * 8;
            float a[2][4], b[8][2];
#pragma unroll
            for (int mt = 0; mt < 2; ++mt) {
                int m = warpM + mt * 16 + gm;
                a[mt][0] = f2tf(As[m][k + kq]);
                a[mt][1] = f2tf(As[m + 8][k + kq]);
                a[mt][2] = f2tf(As[m][k + kq + 4]);
                a[mt][3] = f2tf(As[m + 8][k + kq + 4]);
            }
#pragma unroll
            for (int nt = 0; nt < 8; ++nt) {
                int n = warpN + nt * 8 + gm;
                b[nt][0] = f2tf(Bs[k + kq][n]);
                b[nt][1] = f2tf(Bs[k + kq + 4][n]);
            }
#pragma unroll
            for (int mt = 0; mt < 2; ++mt)
#pragma unroll
                for (int nt = 0; nt < 8; ++nt)
                    mma_tf32(acc[mt][nt], a[mt], b[nt]);
        }
        __syncthreads();
    }

#pragma unroll
    for (int mt = 0; mt < 2; ++mt) {
#pragma unroll
        for (int nt = 0; nt < 8; ++nt) {
            int r0 = rowBase + warpM + mt * 16 + gm;
            int c0 = colBase + warpN + nt * 8 + kq * 2;
#pragma unroll
            for (int half = 0; half < 2; ++half) {
                int r = r0 + half * 8;
                float v0 = acc[mt][nt][half * 2 + 0] + bias[c0];
                float v1 = acc[mt][nt][half * 2 + 1] + bias[c0 + 1];
                if (splitR == 0) {
                    *(float2*)&C[(size_t)r * N + c0] = make_float2(v0, v1);
                } else {
                    // pre-round to tf32 for downstream tensor-core consumers
                    v0 = f2tf(v0); v1 = f2tf(v1);
                    int h = c0 >> 6, d = c0 & 63;
                    int bb = r / splitR, rr = r - bb * splitR;
                    *(float2*)&C[(((size_t)bb * NH + h) * splitR + rr) * HD + d] =
                        make_float2(v0, v1);
                }
            }
        }
    }
}

// ============================================================================
// nt64_tf32: batched C[z][i][j] = sum_d A[z][i][d] * B[zB][j][d]   (K=64, NT)
// Inputs are pre-rounded tf32 -> no cvt. cp.async staging, 2 CTAs/SM.
// mode 0: plain write. mode 1: scores epilogue (scale + bias gathers).
// ============================================================================
__global__ __launch_bounds__(256, 2) void nt64_tf32(
    const float* __restrict__ A, const float* __restrict__ Bm,
    float* __restrict__ C, int N, int bmod, int mode,
    const float* __restrict__ c2p, const float* __restrict__ p2c,
    const int* __restrict__ tbl)
{
    __shared__ float As[128][36];   // [i][d-chunk]
    __shared__ float Bs[128][36];   // [j][d-chunk]

    const int t = threadIdx.x, l = t & 31, w = t >> 5;
    const int gm = l >> 2, kq = l & 3;
    const int warpM = (w >> 1) * 32, warpN = (w & 1) * 64;
    const int batch = blockIdx.z;
    const int iBase = blockIdx.y * 128, jBase = blockIdx.x * 128;

    const float* Ab = A + (size_t)batch * NS * HD;
    const float* Bb = Bm + (size_t)(bmod ? (batch % bmod) : batch) * N * HD;

    float acc[2][8][4];
#pragma unroll
    for (int i = 0; i < 2; ++i)
#pragma unroll
        for (int j = 0; j < 8; ++j)
#pragma unroll
            for (int e = 0; e < 4; ++e) acc[i][j][e] = 0.f;

    const int sr = t >> 1, sc = (t & 1) * 16;

#pragma unroll
    for (int ck = 0; ck < 2; ++ck) {
#pragma unroll
        for (int i = 0; i < 4; ++i) {
            cp16(&As[sr][sc + i * 4], Ab + (size_t)(iBase + sr) * HD + ck * 32 + sc + i * 4);
            cp16(&Bs[sr][sc + i * 4], Bb + (size_t)(jBase + sr) * HD + ck * 32 + sc + i * 4);
        }
        cp_commit();
        cp_wait0();
        __syncthreads();

#pragma unroll
        for (int ks = 0; ks < 4; ++ks) {
            const int k = ks * 8;
            float a[2][4], b[8][2];
#pragma unroll
            for (int mt = 0; mt < 2; ++mt) {
                int m = warpM + mt * 16 + gm;
                a[mt][0] = As[m][k + kq];
                a[mt][1] = As[m + 8][k + kq];
                a[mt][2] = As[m][k + kq + 4];
                a[mt][3] = As[m + 8][k + kq + 4];
            }
#pragma unroll
            for (int nt = 0; nt < 8; ++nt) {
                int n = warpN + nt * 8 + gm;
                b[nt][0] = Bs[n][k + kq];
                b[nt][1] = Bs[n][k + kq + 4];
            }
#pragma unroll
            for (int mt = 0; mt < 2; ++mt)
#pragma unroll
                for (int nt = 0; nt < 8; ++nt)
                    mma_tf32(acc[mt][nt], a[mt], b[nt]);
        }
        __syncthreads();
    }

    float* Cb = C + (size_t)batch * NS * N;
    if (mode == 0) {
#pragma unroll
        for (int mt = 0; mt < 2; ++mt)
#pragma unroll
            for (int nt = 0; nt < 8; ++nt) {
                int r0 = iBase + warpM + mt * 16 + gm;
                int c0 = jBase + warpN + nt * 8 + kq * 2;
#pragma unroll
                for (int half = 0; half < 2; ++half)
                    *(float2*)&Cb[(size_t)(r0 + half * 8) * N + c0] =
                        make_float2(acc[mt][nt][half * 2], acc[mt][nt][half * 2 + 1]);
            }
    } else {
        const float inv192 = 0.07216878364870322f;  // 1/sqrt(64*3)
        const float inv128 = 0.08838834764831845f;  // 1/sqrt(64*2)
        const float* c2pr = c2p + (size_t)batch * NS * NK2;
        const float* p2cr = p2c + (size_t)batch * NS * NK2;
#pragma unroll
        for (int mt = 0; mt < 2; ++mt)
#pragma unroll
            for (int nt = 0; nt < 8; ++nt) {
                int r0 = iBase + warpM + mt * 16 + gm;
                int c0 = jBase + warpN + nt * 8 + kq * 2;
#pragma unroll
                for (int half = 0; half < 2; ++half) {
                    int i = r0 + half * 8;
                    float v[2];
#pragma unroll
                    for (int e = 0; e < 2; ++e) {
                        int j = c0 + e;
                        int delta = i - j;
                        int t1 = tbl[delta + (NS - 1)];
                        int idx1 = min(max(t1 + SPAN, 0), 2 * SPAN - 1);
                        int t2 = tbl[(NS - 1) - delta];
                        int idx2 = min(max(SPAN - t2, 0), 2 * SPAN - 1);
                        float bias = c2pr[(size_t)i * NK2 + idx1] + p2cr[(size_t)j * NK2 + idx2];
                        v[e] = acc[mt][nt][half * 2 + e] * inv192 + bias * inv128;
                    }
                    *(float2*)&Cb[(size_t)i * N + c0] = make_float2(v[0], v[1]);
                }
            }
    }
}

// ============================================================================
// av_tf32: batched ctx[b,i,h*64+d] = sum_j P[z][i][j] * V[z][j][d]
// P and V are pre-rounded tf32 -> no cvt. cp.async staging, 2 CTAs/SM.
// ============================================================================
__global__ __launch_bounds__(256, 2) void av_tf32(
    const float* __restrict__ P, const float* __restrict__ V,
    float* __restrict__ ctx)
{
    __shared__ float As[128][36];  // P tile [i][k]
    __shared__ float Bs[32][72];   // V tile [k][n]

    const int t = threadIdx.x, l = t & 31, w = t >> 5;
    const int gm = l >> 2, kq = l & 3;
    const int warpM = (w >> 1) * 32, warpN = (w & 1) * 32;
    const int batch = blockIdx.y;
    const int bz = batch >> 4, h = batch & 15;
    const int rowBase = blockIdx.x * 128;

    const float* Pb = P + (size_t)batch * NS * NS;
    const float* Vb = V + (size_t)batch * NS * HD;

    float acc[2][4][4];
#pragma unroll
    for (int i = 0; i < 2; ++i)
#pragma unroll
        for (int j = 0; j < 4; ++j)
#pragma unroll
            for (int e = 0; e < 4; ++e) acc[i][j][e] = 0.f;

    const int ar = t >> 1, ac = (t & 1) * 16;
    const int bk = t >> 3, bc = (t & 7) * 4;

    for (int k0 = 0; k0 < NS; k0 += 32) {
#pragma unroll
        for (int i = 0; i < 4; ++i)
            cp16(&As[ar][ac + i * 4], Pb + (size_t)(rowBase + ar) * NS + k0 + ac + i * 4);
#pragma unroll
        for (int i = 0; i < 2; ++i)
            cp16(&Bs[bk][bc + i * 32], Vb + (size_t)(k0 + bk) * HD + bc + i * 32);
        cp_commit();
        cp_wait0();
        __syncthreads();

#pragma unroll
        for (int ks = 0; ks < 4; ++ks) {
            const int k = ks * 8;
            float a[2][4], b[4][2];
#pragma unroll
            for (int mt = 0; mt < 2; ++mt) {
                int m = warpM + mt * 16 + gm;
                a[mt][0] = As[m][k + kq];
                a[mt][1] = As[m + 8][k + kq];
                a[mt][2] = As[m][k + kq + 4];
                a[mt][3] = As[m + 8][k + kq + 4];
            }
#pragma unroll
            for (int nt = 0; nt < 4; ++nt) {
                int n = warpN + nt * 8 + gm;
                b[nt][0] = Bs[k + kq][n];
                b[nt][1] = Bs[k + kq + 4][n];
            }
#pragma unroll
            for (int mt = 0; mt < 2; ++mt)
#pragma unroll
                for (int nt = 0; nt < 4; ++nt)
                    mma_tf32(acc[mt][nt], a[mt], b[nt]);
        }
        __syncthreads();
    }

#pragma unroll
    for (int mt = 0; mt < 2; ++mt)
#pragma unroll
        for (int nt = 0; nt < 4; ++nt) {
            int r0 = rowBase + warpM + mt * 16 + gm;
            int c0 = warpN + nt * 8 + kq * 2;
#pragma unroll
            for (int half = 0; half < 2; ++half) {
                int i = r0 + half * 8;
                *(float2*)&ctx[((size_t)bz * NS + i) * ND + h * HD + c0] =
                    make_float2(acc[mt][nt][half * 2], acc[mt][nt][half * 2 + 1]);
            }
        }
}

// ---------------- softmax (in-place), one block per row; stores tf32-rounded ----
__global__ void softmax_kernel(float* __restrict__ s) {
    size_t row = blockIdx.x;
    float4* p4 = (float4*)(s + row * NS);
    int tid = threadIdx.x;
    float4 x = p4[tid];
    __shared__ float red[256];

    float m = fmaxf(fmaxf(x.x, x.y), fmaxf(x.z, x.w));
    red[tid] = m; __syncthreads();
    for (int o = 128; o > 0; o >>= 1) { if (tid < o) red[tid] = fmaxf(red[tid], red[tid + o]); __syncthreads(); }
    m = red[0]; __syncthreads();

    x.x = expf(x.x - m); x.y = expf(x.y - m); x.z = expf(x.z - m); x.w = expf(x.w - m);
    float sm = x.x + x.y + x.z + x.w;
    red[tid] = sm; __syncthreads();
    for (int o = 128; o > 0; o >>= 1) { if (tid < o) red[tid] += red[tid + o]; __syncthreads(); }
    float inv = 1.0f / red[0];
    // pre-round probs to tf32 for the PV tensor-core GEMM
    x.x = f2tf(x.x * inv); x.y = f2tf(x.y * inv);
    x.z = f2tf(x.z * inv); x.w = f2tf(x.w * inv);
    p4[tid] = x;
}

// ---------------- launch ----------------
extern "C" void kernel_launch(void* const* d_in, const int* in_sizes, int n_in,
                              void* d_out, int out_size) {
    const float* hs    = (const float*)d_in[0];
    const float* Wq    = (const float*)d_in[1];
    const float* bq    = (const float*)d_in[2];
    const float* Wk    = (const float*)d_in[3];
    const float* bk    = (const float*)d_in[4];
    const float* Wv    = (const float*)d_in[5];
    const float* bv    = (const float*)d_in[6];
    const float* Wo    = (const float*)d_in[7];
    const float* bo    = (const float*)d_in[8];
    const float* rel   = (const float*)d_in[9];
    const float* ln_g  = (const float*)d_in[10];
    const float* ln_b  = (const float*)d_in[11];
    const float* Wpk   = (const float*)d_in[12];
    const float* bpk   = (const float*)d_in[13];
    const float* Wpq   = (const float*)d_in[14];
    const float* bpq   = (const float*)d_in[15];
    float* out = (float*)d_out;

    float *p_re, *p_q, *p_k, *p_v, *p_posk, *p_posq, *p_c2p, *p_p2c, *p_sc, *p_ctx;
    int* p_tbl;
    cudaGetSymbolAddress((void**)&p_re, g_re);
    cudaGetSymbolAddress((void**)&p_q, g_q);
    cudaGetSymbolAddress((void**)&p_k, g_k);
    cudaGetSymbolAddress((void**)&p_v, g_v);
    cudaGetSymbolAddress((void**)&p_posk, g_posk);
    cudaGetSymbolAddress((void**)&p_posq, g_posq);
    cudaGetSymbolAddress((void**)&p_c2p, g_c2p);
    cudaGetSymbolAddress((void**)&p_p2c, g_p2c);
    cudaGetSymbolAddress((void**)&p_sc, g_scores);
    cudaGetSymbolAddress((void**)&p_ctx, g_ctx);
    cudaGetSymbolAddress((void**)&p_tbl, g_tbl);

    build_tbl_kernel<<<9, 256>>>(p_tbl);
    ln_kernel<<<NK2, 256>>>(rel, ln_g, ln_b, p_re);

    // projections -> [B,H,S,hd] (tf32-rounded stores)
    mm_bias_tf32<<<dim3(8, 32), 256>>>(hs, Wq, bq, p_q, NB * NS, ND, ND, NS);
    mm_bias_tf32<<<dim3(8, 32), 256>>>(hs, Wk, bk, p_k, NB * NS, ND, ND, NS);
    mm_bias_tf32<<<dim3(8, 32), 256>>>(hs, Wv, bv, p_v, NB * NS, ND, ND, NS);

    // positional projections -> [H,2K,hd] (tf32-rounded stores)
    mm_bias_tf32<<<dim3(8, 4), 256>>>(p_re, Wpk, bpk, p_posk, NK2, ND, ND, NK2);
    mm_bias_tf32<<<dim3(8, 4), 256>>>(p_re, Wpq, bpq, p_posq, NK2, ND, ND, NK2);

    // c2p / p2c
    nt64_tf32<<<dim3(4, 8, 64), 256>>>(p_q, p_posk, p_c2p, NK2, NH, 0, nullptr, nullptr, nullptr);
    nt64_tf32<<<dim3(4, 8, 64), 256>>>(p_k, p_posq, p_p2c, NK2, NH, 0, nullptr, nullptr, nullptr);

    // scores = qk/sqrt(192) + gathered biases / sqrt(128)
    nt64_tf32<<<dim3(8, 8, 64), 256>>>(p_q, p_k, p_sc, NS, 0, 1, p_c2p, p_p2c, p_tbl);

    softmax_kernel<<<NB * NH * NS, 256>>>(p_sc);

    // ctx = probs @ v
    av_tf32<<<dim3(8, 64), 256>>>(p_sc, p_v, p_ctx);

    // out = ctx @ Wo + bo
    mm_bias_tf32<<<dim3(8, 32), 256>>>(p_ctx, Wo, bo, out, NB * NS, ND, ND, 0);
}

// round 5
// speedup vs baseline: 2.7398x; 1.1268x over previous
#include <cuda_runtime.h>
#include <math.h>

// Shapes (fixed by the problem)
#define NB 4
#define NH 16
#define NS 1024
#define ND 1024
#define HD 64
#define NK2 512   // 2 * BUCKETS
#define SPAN 256  // BUCKETS

// ---------------- scratch (device globals; no allocs allowed) ----------------
__device__ float g_re[NK2 * ND];
__device__ float g_q[(size_t)NB * NH * NS * HD];
__device__ float g_k[(size_t)NB * NH * NS * HD];
__device__ float g_v[(size_t)NB * NH * NS * HD];
__device__ float g_posk[NH * NK2 * HD];
__device__ float g_posq[NH * NK2 * HD];
__device__ float g_c2p[(size_t)NB * NH * NS * NK2];
__device__ float g_p2c[(size_t)NB * NH * NS * NK2];
__device__ float g_scores[(size_t)NB * NH * NS * NS];
__device__ float g_ctx[(size_t)NB * NS * ND];
__device__ int   g_tbl[2 * NS - 1];

// ---------------- helpers ----------------
__device__ __forceinline__ float f2tf(float x) {
    unsigned u;
    asm("cvt.rna.tf32.f32 %0, %1;" : "=r"(u) : "f"(x));
    return __uint_as_float(u);
}

__device__ __forceinline__ void mma_tf32(float* c, const float* a, const float* b) {
    asm volatile("mma.sync.aligned.m16n8k8.row.col.f32.tf32.tf32.f32 "
                 "{%0,%1,%2,%3}, {%4,%5,%6,%7}, {%8,%9}, {%0,%1,%2,%3};\n"
                 : "+f"(c[0]), "+f"(c[1]), "+f"(c[2]), "+f"(c[3])
                 : "r"(__float_as_uint(a[0])), "r"(__float_as_uint(a[1])),
                   "r"(__float_as_uint(a[2])), "r"(__float_as_uint(a[3])),
                   "r"(__float_as_uint(b[0])), "r"(__float_as_uint(b[1])));
}

__device__ __forceinline__ void cp16(float* dst, const float* src) {
    unsigned s = (unsigned)__cvta_generic_to_shared(dst);
    asm volatile("cp.async.cg.shared.global [%0], [%1], 16;" :: "r"(s), "l"(src));
}
__device__ __forceinline__ void cp_commit() { asm volatile("cp.async.commit_group;"); }
__device__ __forceinline__ void cp_wait0()  { asm volatile("cp.async.wait_group 0;"); }
__device__ __forceinline__ void cp_wait1()  { asm volatile("cp.async.wait_group 1;"); }

// ---------------- bucket table ----------------
__global__ void build_tbl_kernel(int* tbl) {
    int i = blockIdx.x * blockDim.x + threadIdx.x;
    if (i >= 2 * NS - 1) return;
    int rel = i - (NS - 1);
    const float mid = 128.0f;
    float signf = (rel > 0) ? 1.0f : (rel < 0 ? -1.0f : 0.0f);
    float abs_pos = (rel < 128 && rel > -128) ? 127.0f : fabsf((float)rel);
    float bucket;
    if (abs_pos <= mid) {
        bucket = (float)rel;
    } else {
        const float LOGC = 1.3843393289f;  // log(511/128) as f32
        float log_pos = ceilf(logf(abs_pos / mid) / LOGC * 127.0f) + mid;
        bucket = log_pos * signf;
    }
    tbl[i] = (int)bucket;
}

// ---------------- LayerNorm for rel_emb [512,1024] ----------------
__global__ void ln_kernel(const float* __restrict__ x, const float* __restrict__ g,
                          const float* __restrict__ b, float* __restrict__ y) {
    int row = blockIdx.x;
    const float* xr = x + (size_t)row * ND;
    __shared__ float red[256];
    int tid = threadIdx.x;

    float s = 0.f;
    for (int i = tid; i < ND; i += 256) s += xr[i];
    red[tid] = s; __syncthreads();
    for (int o = 128; o > 0; o >>= 1) { if (tid < o) red[tid] += red[tid + o]; __syncthreads(); }
    float mu = red[0] * (1.0f / ND);
    __syncthreads();

    float v = 0.f;
    for (int i = tid; i < ND; i += 256) { float d = xr[i] - mu; v += d * d; }
    red[tid] = v; __syncthreads();
    for (int o = 128; o > 0; o >>= 1) { if (tid < o) red[tid] += red[tid + o]; __syncthreads(); }
    float var = red[0] * (1.0f / ND);
    float inv = 1.0f / sqrtf(var + 1e-5f);

    for (int i = tid; i < ND; i += 256)
        y[(size_t)row * ND + i] = (xr[i] - mu) * inv * g[i] + b[i];
}

// ============================================================================
// mm_bias_tf32: C[M,N] = A[M,K] @ W[K,N] + bias  (tf32 TC, 2-stage cp.async)
// blockIdx.z selects among up to 3 (W,bias,C) sets (merged QKV / pos launches).
// 128x128 block tile, K-chunk 16, 256 thr / 8 warps, warp tile 32x64.
// splitR == 0: plain row-major store; else head-split store (+tf32 round).
// ============================================================================
__global__ __launch_bounds__(256, 2) void mm_bias_tf32(
    const float* __restrict__ A,
    const float* __restrict__ W0, const float* __restrict__ W1, const float* __restrict__ W2,
    const float* __restrict__ b0, const float* __restrict__ b1, const float* __restrict__ b2,
    float* __restrict__ C0, float* __restrict__ C1, float* __restrict__ C2,
    int M, int N, int K, int splitR)
{
    __shared__ float As[2][128][20];   // [m][k]  (stride 20 ≡ 4 mod 32 -> conflict-free)
    __shared__ float Bs[2][16][136];   // [k][n]  (stride 136 ≡ 8 mod 32 -> conflict-free)

    const int z = blockIdx.z;
    const float* W    = (z == 0) ? W0 : (z == 1) ? W1 : W2;
    const float* bias = (z == 0) ? b0 : (z == 1) ? b1 : b2;
    float*       C    = (z == 0) ? C0 : (z == 1) ? C1 : C2;

    const int t = threadIdx.x, l = t & 31, w = t >> 5;
    const int gm = l >> 2, kq = l & 3;
    const int warpM = (w >> 1) * 32, warpN = (w & 1) * 64;
    const int rowBase = blockIdx.y * 128, colBase = blockIdx.x * 128;

    float acc[2][8][4];
#pragma unroll
    for (int i = 0; i < 2; ++i)
#pragma unroll
        for (int j = 0; j < 8; ++j)
#pragma unroll
            for (int e = 0; e < 4; ++e) acc[i][j][e] = 0.f;

    const int ar = t >> 1, ac = (t & 1) * 8;   // A stage: 128 rows x 16 cols
    const int bk = t >> 4, bc = (t & 15) * 8;  // B stage: 16 rows x 128 cols

    const int NCH = K / 16;
    // prologue: stage 0
    cp16(&As[0][ar][ac],     A + (size_t)(rowBase + ar) * K + ac);
    cp16(&As[0][ar][ac + 4], A + (size_t)(rowBase + ar) * K + ac + 4);
    cp16(&Bs[0][bk][bc],     W + (size_t)bk * N + colBase + bc);
    cp16(&Bs[0][bk][bc + 4], W + (size_t)bk * N + colBase + bc + 4);
    cp_commit();

    for (int c = 0; c < NCH; ++c) {
        if (c + 1 < NCH) {
            int k0 = (c + 1) * 16, s = (c + 1) & 1;
            cp16(&As[s][ar][ac],     A + (size_t)(rowBase + ar) * K + k0 + ac);
            cp16(&As[s][ar][ac + 4], A + (size_t)(rowBase + ar) * K + k0 + ac + 4);
            cp16(&Bs[s][bk][bc],     W + (size_t)(k0 + bk) * N + colBase + bc);
            cp16(&Bs[s][bk][bc + 4], W + (size_t)(k0 + bk) * N + colBase + bc + 4);
            cp_commit();
            cp_wait1();
        } else {
            cp_wait0();
        }
        __syncthreads();

        const int s = c & 1;
#pragma unroll
        for (int ks = 0; ks < 2; ++ks) {
            const int k = ks * 8;
            float a[2][4], b[8][2];
#pragma unroll
            for (int mt = 0; mt < 2; ++mt) {
                int m = warpM + mt * 16 + gm;
                a[mt][0] = f2tf(As[s][m][k + kq]);
                a[mt][1] = f2tf(As[s][m + 8][k + kq]);
                a[mt][2] = f2tf(As[s][m][k + kq + 4]);
                a[mt][3] = f2tf(As[s][m + 8][k + kq + 4]);
            }
#pragma unroll
            for (int nt = 0; nt < 8; ++nt) {
                int n = warpN + nt * 8 + gm;
                b[nt][0] = f2tf(Bs[s][k + kq][n]);
                b[nt][1] = f2tf(Bs[s][k + kq + 4][n]);
            }
#pragma unroll
            for (int mt = 0; mt < 2; ++mt)
#pragma unroll
                for (int nt = 0; nt < 8; ++nt)
                    mma_tf32(acc[mt][nt], a[mt], b[nt]);
        }
        __syncthreads();
    }

#pragma unroll
    for (int mt = 0; mt < 2; ++mt) {
#pragma unroll
        for (int nt = 0; nt < 8; ++nt) {
            int r0 = rowBase + warpM + mt * 16 + gm;
            int c0 = colBase + warpN + nt * 8 + kq * 2;
#pragma unroll
            for (int half = 0; half < 2; ++half) {
                int r = r0 + half * 8;
                float v0 = acc[mt][nt][half * 2 + 0] + bias[c0];
                float v1 = acc[mt][nt][half * 2 + 1] + bias[c0 + 1];
                if (splitR == 0) {
                    *(float2*)&C[(size_t)r * N + c0] = make_float2(v0, v1);
                } else {
                    v0 = f2tf(v0); v1 = f2tf(v1);   // pre-round for TC consumers
                    int h = c0 >> 6, d = c0 & 63;
                    int bb = r / splitR, rr = r - bb * splitR;
                    *(float2*)&C[(((size_t)bb * NH + h) * splitR + rr) * HD + d] =
                        make_float2(v0, v1);
                }
            }
        }
    }
}

// ============================================================================
// nt64_tf32: batched C[z][i][j] = sum_d A[z][i][d] * B[zB][j][d]  (K=64, NT)
// 2-stage cp.async, K-chunk 16 (4 chunks). Inputs pre-rounded tf32.
// mode 0: plain write. mode 1: scores epilogue (scale + bias gathers).
// ============================================================================
__global__ __launch_bounds__(256, 2) void nt64_tf32(
    const float* __restrict__ A, const float* __restrict__ Bm,
    float* __restrict__ C, int N, int bmod, int mode,
    const float* __restrict__ c2p, const float* __restrict__ p2c,
    const int* __restrict__ tbl)
{
    __shared__ float As[2][128][20];   // [i][d-chunk]
    __shared__ float Bs[2][128][20];   // [j][d-chunk]

    const int t = threadIdx.x, l = t & 31, w = t >> 5;
    const int gm = l >> 2, kq = l & 3;
    const int warpM = (w >> 1) * 32, warpN = (w & 1) * 64;
    const int batch = blockIdx.z;
    const int iBase = blockIdx.y * 128, jBase = blockIdx.x * 128;

    const float* Ab = A + (size_t)batch * NS * HD;
    const float* Bb = Bm + (size_t)(bmod ? (batch % bmod) : batch) * N * HD;

    float acc[2][8][4];
#pragma unroll
    for (int i = 0; i < 2; ++i)
#pragma unroll
        for (int j = 0; j < 8; ++j)
#pragma unroll
            for (int e = 0; e < 4; ++e) acc[i][j][e] = 0.f;

    const int sr = t >> 1, sc = (t & 1) * 8;

    cp16(&As[0][sr][sc],     Ab + (size_t)(iBase + sr) * HD + sc);
    cp16(&As[0][sr][sc + 4], Ab + (size_t)(iBase + sr) * HD + sc + 4);
    cp16(&Bs[0][sr][sc],     Bb + (size_t)(jBase + sr) * HD + sc);
    cp16(&Bs[0][sr][sc + 4], Bb + (size_t)(jBase + sr) * HD + sc + 4);
    cp_commit();

#pragma unroll
    for (int c = 0; c < 4; ++c) {
        if (c + 1 < 4) {
            int d0 = (c + 1) * 16, s = (c + 1) & 1;
            cp16(&As[s][sr][sc],     Ab + (size_t)(iBase + sr) * HD + d0 + sc);
            cp16(&As[s][sr][sc + 4], Ab + (size_t)(iBase + sr) * HD + d0 + sc + 4);
            cp16(&Bs[s][sr][sc],     Bb + (size_t)(jBase + sr) * HD + d0 + sc);
            cp16(&Bs[s][sr][sc + 4], Bb + (size_t)(jBase + sr) * HD + d0 + sc + 4);
            cp_commit();
            cp_wait1();
        } else {
            cp_wait0();
        }
        __syncthreads();

        const int s = c & 1;
#pragma unroll
        for (int ks = 0; ks < 2; ++ks) {
            const int k = ks * 8;
            float a[2][4], b[8][2];
#pragma unroll
            for (int mt = 0; mt < 2; ++mt) {
                int m = warpM + mt * 16 + gm;
                a[mt][0] = As[s][m][k + kq];
                a[mt][1] = As[s][m + 8][k + kq];
                a[mt][2] = As[s][m][k + kq + 4];
                a[mt][3] = As[s][m + 8][k + kq + 4];
            }
#pragma unroll
            for (int nt = 0; nt < 8; ++nt) {
                int n = warpN + nt * 8 + gm;
                b[nt][0] = Bs[s][n][k + kq];
                b[nt][1] = Bs[s][n][k + kq + 4];
            }
#pragma unroll
            for (int mt = 0; mt < 2; ++mt)
#pragma unroll
                for (int nt = 0; nt < 8; ++nt)
                    mma_tf32(acc[mt][nt], a[mt], b[nt]);
        }
        __syncthreads();
    }

    float* Cb = C + (size_t)batch * NS * N;
    if (mode == 0) {
#pragma unroll
        for (int mt = 0; mt < 2; ++mt)
#pragma unroll
            for (int nt = 0; nt < 8; ++nt) {
                int r0 = iBase + warpM + mt * 16 + gm;
                int c0 = jBase + warpN + nt * 8 + kq * 2;
#pragma unroll
                for (int half = 0; half < 2; ++half)
                    *(float2*)&Cb[(size_t)(r0 + half * 8) * N + c0] =
                        make_float2(acc[mt][nt][half * 2], acc[mt][nt][half * 2 + 1]);
            }
    } else {
        const float inv192 = 0.07216878364870322f;  // 1/sqrt(64*3)
        const float inv128 = 0.08838834764831845f;  // 1/sqrt(64*2)
        const float* c2pr = c2p + (size_t)batch * NS * NK2;
        const float* p2cr = p2c + (size_t)batch * NS * NK2;
#pragma unroll
        for (int mt = 0; mt < 2; ++mt)
#pragma unroll
            for (int nt = 0; nt < 8; ++nt) {
                int r0 = iBase + warpM + mt * 16 + gm;
                int c0 = jBase + warpN + nt * 8 + kq * 2;
#pragma unroll
                for (int half = 0; half < 2; ++half) {
                    int i = r0 + half * 8;
                    float v[2];
#pragma unroll
                    for (int e = 0; e < 2; ++e) {
                        int j = c0 + e;
                        int delta = i - j;
                        int t1 = tbl[delta + (NS - 1)];
                        int idx1 = min(max(t1 + SPAN, 0), 2 * SPAN - 1);
                        int t2 = tbl[(NS - 1) - delta];
                        int idx2 = min(max(SPAN - t2, 0), 2 * SPAN - 1);
                        float bias = c2pr[(size_t)i * NK2 + idx1] + p2cr[(size_t)j * NK2 + idx2];
                        v[e] = acc[mt][nt][half * 2 + e] * inv192 + bias * inv128;
                    }
                    *(float2*)&Cb[(size_t)i * N + c0] = make_float2(v[0], v[1]);
                }
            }
    }
}

// ============================================================================
// av_tf32: batched ctx[b,i,h*64+d] = sum_j P[z][i][j] * V[z][j][d]
// 2-stage cp.async, K-chunk 16. P and V pre-rounded tf32.
// ============================================================================
__global__ __launch_bounds__(256, 2) void av_tf32(
    const float* __restrict__ P, const float* __restrict__ V,
    float* __restrict__ ctx)
{
    __shared__ float As[2][128][20];  // P tile [i][k]
    __shared__ float Bs[2][16][72];   // V tile [k][n]  (stride 72 ≡ 8 mod 32)

    const int t = threadIdx.x, l = t & 31, w = t >> 5;
    const int gm = l >> 2, kq = l & 3;
    const int warpM = (w >> 1) * 32, warpN = (w & 1) * 32;
    const int batch = blockIdx.y;
    const int bz = batch >> 4, h = batch & 15;
    const int rowBase = blockIdx.x * 128;

    const float* Pb = P + (size_t)batch * NS * NS;
    const float* Vb = V + (size_t)batch * NS * HD;

    float acc[2][4][4];
#pragma unroll
    for (int i = 0; i < 2; ++i)
#pragma unroll
        for (int j = 0; j < 4; ++j)
#pragma unroll
            for (int e = 0; e < 4; ++e) acc[i][j][e] = 0.f;

    const int ar = t >> 1, ac = (t & 1) * 8;
    const int bk = t >> 4, bc = (t & 15) * 4;

    cp16(&As[0][ar][ac],     Pb + (size_t)(rowBase + ar) * NS + ac);
    cp16(&As[0][ar][ac + 4], Pb + (size_t)(rowBase + ar) * NS + ac + 4);
    cp16(&Bs[0][bk][bc],     Vb + (size_t)bk * HD + bc);
    cp_commit();

    const int NCH = NS / 16;
    for (int c = 0; c < NCH; ++c) {
        if (c + 1 < NCH) {
            int k0 = (c + 1) * 16, s = (c + 1) & 1;
            cp16(&As[s][ar][ac],     Pb + (size_t)(rowBase + ar) * NS + k0 + ac);
            cp16(&As[s][ar][ac + 4], Pb + (size_t)(rowBase + ar) * NS + k0 + ac + 4);
            cp16(&Bs[s][bk][bc],     Vb + (size_t)(k0 + bk) * HD + bc);
            cp_commit();
            cp_wait1();
        } else {
            cp_wait0();
        }
        __syncthreads();

        const int s = c & 1;
#pragma unroll
        for (int ks = 0; ks < 2; ++ks) {
            const int k = ks * 8;
            float a[2][4], b[4][2];
#pragma unroll
            for (int mt = 0; mt < 2; ++mt) {
                int m = warpM + mt * 16 + gm;
                a[mt][0] = As[s][m][k + kq];
                a[mt][1] = As[s][m + 8][k + kq];
                a[mt][2] = As[s][m][k + kq + 4];
                a[mt][3] = As[s][m + 8][k + kq + 4];
            }
#pragma unroll
            for (int nt = 0; nt < 4; ++nt) {
                int n = warpN + nt * 8 + gm;
                b[nt][0] = Bs[s][k + kq][n];
                b[nt][1] = Bs[s][k + kq + 4][n];
            }
#pragma unroll
            for (int mt = 0; mt < 2; ++mt)
#pragma unroll
                for (int nt = 0; nt < 4; ++nt)
                    mma_tf32(acc[mt][nt], a[mt], b[nt]);
        }
        __syncthreads();
    }

#pragma unroll
    for (int mt = 0; mt < 2; ++mt)
#pragma unroll
        for (int nt = 0; nt < 4; ++nt) {
            int r0 = rowBase + warpM + mt * 16 + gm;
            int c0 = warpN + nt * 8 + kq * 2;
#pragma unroll
            for (int half = 0; half < 2; ++half) {
                int i = r0 + half * 8;
                *(float2*)&ctx[((size_t)bz * NS + i) * ND + h * HD + c0] =
                    make_float2(acc[mt][nt][half * 2], acc[mt][nt][half * 2 + 1]);
            }
        }
}

// ---------------- softmax (in-place), one block per row; stores tf32-rounded ----
__global__ void softmax_kernel(float* __restrict__ s) {
    size_t row = blockIdx.x;
    float4* p4 = (float4*)(s + row * NS);
    int tid = threadIdx.x;
    float4 x = p4[tid];
    __shared__ float red[256];

    float m = fmaxf(fmaxf(x.x, x.y), fmaxf(x.z, x.w));
    red[tid] = m; __syncthreads();
    for (int o = 128; o > 0; o >>= 1) { if (tid < o) red[tid] = fmaxf(red[tid], red[tid + o]); __syncthreads(); }
    m = red[0]; __syncthreads();

    x.x = expf(x.x - m); x.y = expf(x.y - m); x.z = expf(x.z - m); x.w = expf(x.w - m);
    float sm = x.x + x.y + x.z + x.w;
    red[tid] = sm; __syncthreads();
    for (int o = 128; o > 0; o >>= 1) { if (tid < o) red[tid] += red[tid + o]; __syncthreads(); }
    float inv = 1.0f / red[0];
    x.x = f2tf(x.x * inv); x.y = f2tf(x.y * inv);
    x.z = f2tf(x.z * inv); x.w = f2tf(x.w * inv);
    p4[tid] = x;
}

// ---------------- launch ----------------
extern "C" void kernel_launch(void* const* d_in, const int* in_sizes, int n_in,
                              void* d_out, int out_size) {
    const float* hs    = (const float*)d_in[0];
    const float* Wq    = (const float*)d_in[1];
    const float* bq    = (const float*)d_in[2];
    const float* Wk    = (const float*)d_in[3];
    const float* bk    = (const float*)d_in[4];
    const float* Wv    = (const float*)d_in[5];
    const float* bv    = (const float*)d_in[6];
    const float* Wo    = (const float*)d_in[7];
    const float* bo    = (const float*)d_in[8];
    const float* rel   = (const float*)d_in[9];
    const float* ln_g  = (const float*)d_in[10];
    const float* ln_b  = (const float*)d_in[11];
    const float* Wpk   = (const float*)d_in[12];
    const float* bpk   = (const float*)d_in[13];
    const float* Wpq   = (const float*)d_in[14];
    const float* bpq   = (const float*)d_in[15];
    float* out = (float*)d_out;

    float *p_re, *p_q, *p_k, *p_v, *p_posk, *p_posq, *p_c2p, *p_p2c, *p_sc, *p_ctx;
    int* p_tbl;
    cudaGetSymbolAddress((void**)&p_re, g_re);
    cudaGetSymbolAddress((void**)&p_q, g_q);
    cudaGetSymbolAddress((void**)&p_k, g_k);
    cudaGetSymbolAddress((void**)&p_v, g_v);
    cudaGetSymbolAddress((void**)&p_posk, g_posk);
    cudaGetSymbolAddress((void**)&p_posq, g_posq);
    cudaGetSymbolAddress((void**)&p_c2p, g_c2p);
    cudaGetSymbolAddress((void**)&p_p2c, g_p2c);
    cudaGetSymbolAddress((void**)&p_sc, g_scores);
    cudaGetSymbolAddress((void**)&p_ctx, g_ctx);
    cudaGetSymbolAddress((void**)&p_tbl, g_tbl);

    build_tbl_kernel<<<9, 256>>>(p_tbl);
    ln_kernel<<<NK2, 256>>>(rel, ln_g, ln_b, p_re);

    // merged Q/K/V projections -> [B,H,S,hd] (tf32-rounded stores)
    mm_bias_tf32<<<dim3(8, 32, 3), 256>>>(hs, Wq, Wk, Wv, bq, bk, bv,
                                          p_q, p_k, p_v, NB * NS, ND, ND, NS);

    // merged positional projections -> [H,2K,hd]
    mm_bias_tf32<<<dim3(8, 4, 2), 256>>>(p_re, Wpk, Wpq, Wpq, bpk, bpq, bpq,
                                         p_posk, p_posq, p_posq, NK2, ND, ND, NK2);

    // c2p / p2c
    nt64_tf32<<<dim3(4, 8, 64), 256>>>(p_q, p_posk, p_c2p, NK2, NH, 0, nullptr, nullptr, nullptr);
    nt64_tf32<<<dim3(4, 8, 64), 256>>>(p_k, p_posq, p_p2c, NK2, NH, 0, nullptr, nullptr, nullptr);

    // scores = qk/sqrt(192) + gathered biases / sqrt(128)
    nt64_tf32<<<dim3(8, 8, 64), 256>>>(p_q, p_k, p_sc, NS, 0, 1, p_c2p, p_p2c, p_tbl);

    softmax_kernel<<<NB * NH * NS, 256>>>(p_sc);

    // ctx = probs @ v
    av_tf32<<<dim3(8, 64), 256>>>(p_sc, p_v, p_ctx);

    // out = ctx @ Wo + bo
    mm_bias_tf32<<<dim3(8, 32, 1), 256>>>(p_ctx, Wo, Wo, Wo, bo, bo, bo,
                                          out, out, out, NB * NS, ND, ND, 0);
}

// round 6
// speedup vs baseline: 3.1225x; 1.1397x over previous
#include <cuda_runtime.h>
#include <math.h>

// Shapes (fixed by the problem)
#define NB 4
#define NH 16
#define NS 1024
#define ND 1024
#define HD 64
#define NK2 512   // 2 * BUCKETS
#define SPAN 256  // BUCKETS

// ---------------- scratch (device globals; no allocs allowed) ----------------
__device__ float g_re[NK2 * ND];
__device__ float g_q[(size_t)NB * NH * NS * HD];
__device__ float g_k[(size_t)NB * NH * NS * HD];
__device__ float g_v[(size_t)NB * NH * NS * HD];
__device__ float g_posk[NH * NK2 * HD];
__device__ float g_posq[NH * NK2 * HD];
__device__ float g_c2p[(size_t)NB * NH * NS * NK2];
__device__ float g_p2c[(size_t)NB * NH * NS * NK2];
__device__ float g_ctx[(size_t)NB * NS * ND];
__device__ int   g_tbl[2 * NS - 1];

// ---------------- helpers ----------------
__device__ __forceinline__ float f2tf(float x) {
    unsigned u;
    asm("cvt.rna.tf32.f32 %0, %1;" : "=r"(u) : "f"(x));
    return __uint_as_float(u);
}

__device__ __forceinline__ void mma_tf32(float* c, const float* a, const float* b) {
    asm volatile("mma.sync.aligned.m16n8k8.row.col.f32.tf32.tf32.f32 "
                 "{%0,%1,%2,%3}, {%4,%5,%6,%7}, {%8,%9}, {%0,%1,%2,%3};\n"
                 : "+f"(c[0]), "+f"(c[1]), "+f"(c[2]), "+f"(c[3])
                 : "r"(__float_as_uint(a[0])), "r"(__float_as_uint(a[1])),
                   "r"(__float_as_uint(a[2])), "r"(__float_as_uint(a[3])),
                   "r"(__float_as_uint(b[0])), "r"(__float_as_uint(b[1])));
}

__device__ __forceinline__ void cp16(float* dst, const float* src) {
    unsigned s = (unsigned)__cvta_generic_to_shared(dst);
    asm volatile("cp.async.cg.shared.global [%0], [%1], 16;" :: "r"(s), "l"(src));
}
__device__ __forceinline__ void cp_commit() { asm volatile("cp.async.commit_group;"); }
__device__ __forceinline__ void cp_wait0()  { asm volatile("cp.async.wait_group 0;"); }
__device__ __forceinline__ void cp_wait1()  { asm volatile("cp.async.wait_group 1;"); }

// ---------------- bucket table ----------------
__global__ void build_tbl_kernel(int* tbl) {
    int i = blockIdx.x * blockDim.x + threadIdx.x;
    if (i >= 2 * NS - 1) return;
    int rel = i - (NS - 1);
    const float mid = 128.0f;
    float signf = (rel > 0) ? 1.0f : (rel < 0 ? -1.0f : 0.0f);
    float abs_pos = (rel < 128 && rel > -128) ? 127.0f : fabsf((float)rel);
    float bucket;
    if (abs_pos <= mid) {
        bucket = (float)rel;
    } else {
        const float LOGC = 1.3843393289f;  // log(511/128) as f32
        float log_pos = ceilf(logf(abs_pos / mid) / LOGC * 127.0f) + mid;
        bucket = log_pos * signf;
    }
    tbl[i] = (int)bucket;
}

// ---------------- LayerNorm for rel_emb [512,1024] ----------------
__global__ void ln_kernel(const float* __restrict__ x, const float* __restrict__ g,
                          const float* __restrict__ b, float* __restrict__ y) {
    int row = blockIdx.x;
    const float* xr = x + (size_t)row * ND;
    __shared__ float red[256];
    int tid = threadIdx.x;

    float s = 0.f;
    for (int i = tid; i < ND; i += 256) s += xr[i];
    red[tid] = s; __syncthreads();
    for (int o = 128; o > 0; o >>= 1) { if (tid < o) red[tid] += red[tid + o]; __syncthreads(); }
    float mu = red[0] * (1.0f / ND);
    __syncthreads();

    float v = 0.f;
    for (int i = tid; i < ND; i += 256) { float d = xr[i] - mu; v += d * d; }
    red[tid] = v; __syncthreads();
    for (int o = 128; o > 0; o >>= 1) { if (tid < o) red[tid] += red[tid + o]; __syncthreads(); }
    float var = red[0] * (1.0f / ND);
    float inv = 1.0f / sqrtf(var + 1e-5f);

    for (int i = tid; i < ND; i += 256)
        y[(size_t)row * ND + i] = (xr[i] - mu) * inv * g[i] + b[i];
}

// ============================================================================
// mm_bias_tf32: C[M,N] = A[M,K] @ W[K,N] + bias  (tf32 TC, 2-stage cp.async)
// blockIdx.z selects among up to 3 (W,bias,C) sets.
// ============================================================================
__global__ __launch_bounds__(256, 2) void mm_bias_tf32(
    const float* __restrict__ A,
    const float* __restrict__ W0, const float* __restrict__ W1, const float* __restrict__ W2,
    const float* __restrict__ b0, const float* __restrict__ b1, const float* __restrict__ b2,
    float* __restrict__ C0, float* __restrict__ C1, float* __restrict__ C2,
    int M, int N, int K, int splitR)
{
    __shared__ float As[2][128][20];
    __shared__ float Bs[2][16][136];

    const int z = blockIdx.z;
    const float* W    = (z == 0) ? W0 : (z == 1) ? W1 : W2;
    const float* bias = (z == 0) ? b0 : (z == 1) ? b1 : b2;
    float*       C    = (z == 0) ? C0 : (z == 1) ? C1 : C2;

    const int t = threadIdx.x, l = t & 31, w = t >> 5;
    const int gm = l >> 2, kq = l & 3;
    const int warpM = (w >> 1) * 32, warpN = (w & 1) * 64;
    const int rowBase = blockIdx.y * 128, colBase = blockIdx.x * 128;

    float acc[2][8][4];
#pragma unroll
    for (int i = 0; i < 2; ++i)
#pragma unroll
        for (int j = 0; j < 8; ++j)
#pragma unroll
            for (int e = 0; e < 4; ++e) acc[i][j][e] = 0.f;

    const int ar = t >> 1, ac = (t & 1) * 8;
    const int bk = t >> 4, bc = (t & 15) * 8;

    const int NCH = K / 16;
    cp16(&As[0][ar][ac],     A + (size_t)(rowBase + ar) * K + ac);
    cp16(&As[0][ar][ac + 4], A + (size_t)(rowBase + ar) * K + ac + 4);
    cp16(&Bs[0][bk][bc],     W + (size_t)bk * N + colBase + bc);
    cp16(&Bs[0][bk][bc + 4], W + (size_t)bk * N + colBase + bc + 4);
    cp_commit();

    for (int c = 0; c < NCH; ++c) {
        if (c + 1 < NCH) {
            int k0 = (c + 1) * 16, s = (c + 1) & 1;
            cp16(&As[s][ar][ac],     A + (size_t)(rowBase + ar) * K + k0 + ac);
            cp16(&As[s][ar][ac + 4], A + (size_t)(rowBase + ar) * K + k0 + ac + 4);
            cp16(&Bs[s][bk][bc],     W + (size_t)(k0 + bk) * N + colBase + bc);
            cp16(&Bs[s][bk][bc + 4], W + (size_t)(k0 + bk) * N + colBase + bc + 4);
            cp_commit();
            cp_wait1();
        } else {
            cp_wait0();
        }
        __syncthreads();

        const int s = c & 1;
#pragma unroll
        for (int ks = 0; ks < 2; ++ks) {
            const int k = ks * 8;
            float a[2][4], b[8][2];
#pragma unroll
            for (int mt = 0; mt < 2; ++mt) {
                int m = warpM + mt * 16 + gm;
                a[mt][0] = f2tf(As[s][m][k + kq]);
                a[mt][1] = f2tf(As[s][m + 8][k + kq]);
                a[mt][2] = f2tf(As[s][m][k + kq + 4]);
                a[mt][3] = f2tf(As[s][m + 8][k + kq + 4]);
            }
#pragma unroll
            for (int nt = 0; nt < 8; ++nt) {
                int n = warpN + nt * 8 + gm;
                b[nt][0] = f2tf(Bs[s][k + kq][n]);
                b[nt][1] = f2tf(Bs[s][k + kq + 4][n]);
            }
#pragma unroll
            for (int mt = 0; mt < 2; ++mt)
#pragma unroll
                for (int nt = 0; nt < 8; ++nt)
                    mma_tf32(acc[mt][nt], a[mt], b[nt]);
        }
        __syncthreads();
    }

#pragma unroll
    for (int mt = 0; mt < 2; ++mt) {
#pragma unroll
        for (int nt = 0; nt < 8; ++nt) {
            int r0 = rowBase + warpM + mt * 16 + gm;
            int c0 = colBase + warpN + nt * 8 + kq * 2;
#pragma unroll
            for (int half = 0; half < 2; ++half) {
                int r = r0 + half * 8;
                float v0 = acc[mt][nt][half * 2 + 0] + bias[c0];
                float v1 = acc[mt][nt][half * 2 + 1] + bias[c0 + 1];
                if (splitR == 0) {
                    *(float2*)&C[(size_t)r * N + c0] = make_float2(v0, v1);
                } else {
                    v0 = f2tf(v0); v1 = f2tf(v1);
                    int h = c0 >> 6, d = c0 & 63;
                    int bb = r / splitR, rr = r - bb * splitR;
                    *(float2*)&C[(((size_t)bb * NH + h) * splitR + rr) * HD + d] =
                        make_float2(v0, v1);
                }
            }
        }
    }
}

// ============================================================================
// nt64_tf32: batched C[z][i][j] = sum_d A[z][i][d] * B[z%bmod][j][d]  (K=64, NT)
// Used for c2p / p2c (N = 512). Inputs pre-rounded tf32.
// ============================================================================
__global__ __launch_bounds__(256, 2) void nt64_tf32(
    const float* __restrict__ A, const float* __restrict__ Bm,
    float* __restrict__ C, int N, int bmod)
{
    __shared__ float As[2][128][20];
    __shared__ float Bs[2][128][20];

    const int t = threadIdx.x, l = t & 31, w = t >> 5;
    const int gm = l >> 2, kq = l & 3;
    const int warpM = (w >> 1) * 32, warpN = (w & 1) * 64;
    const int batch = blockIdx.z;
    const int iBase = blockIdx.y * 128, jBase = blockIdx.x * 128;

    const float* Ab = A + (size_t)batch * NS * HD;
    const float* Bb = Bm + (size_t)(batch % bmod) * N * HD;

    float acc[2][8][4];
#pragma unroll
    for (int i = 0; i < 2; ++i)
#pragma unroll
        for (int j = 0; j < 8; ++j)
#pragma unroll
            for (int e = 0; e < 4; ++e) acc[i][j][e] = 0.f;

    const int sr = t >> 1, sc = (t & 1) * 8;

    cp16(&As[0][sr][sc],     Ab + (size_t)(iBase + sr) * HD + sc);
    cp16(&As[0][sr][sc + 4], Ab + (size_t)(iBase + sr) * HD + sc + 4);
    cp16(&Bs[0][sr][sc],     Bb + (size_t)(jBase + sr) * HD + sc);
    cp16(&Bs[0][sr][sc + 4], Bb + (size_t)(jBase + sr) * HD + sc + 4);
    cp_commit();

#pragma unroll
    for (int c = 0; c < 4; ++c) {
        if (c + 1 < 4) {
            int d0 = (c + 1) * 16, s = (c + 1) & 1;
            cp16(&As[s][sr][sc],     Ab + (size_t)(iBase + sr) * HD + d0 + sc);
            cp16(&As[s][sr][sc + 4], Ab + (size_t)(iBase + sr) * HD + d0 + sc + 4);
            cp16(&Bs[s][sr][sc],     Bb + (size_t)(jBase + sr) * HD + d0 + sc);
            cp16(&Bs[s][sr][sc + 4], Bb + (size_t)(jBase + sr) * HD + d0 + sc + 4);
            cp_commit();
            cp_wait1();
        } else {
            cp_wait0();
        }
        __syncthreads();

        const int s = c & 1;
#pragma unroll
        for (int ks = 0; ks < 2; ++ks) {
            const int k = ks * 8;
            float a[2][4], b[8][2];
#pragma unroll
            for (int mt = 0; mt < 2; ++mt) {
                int m = warpM + mt * 16 + gm;
                a[mt][0] = As[s][m][k + kq];
                a[mt][1] = As[s][m + 8][k + kq];
                a[mt][2] = As[s][m][k + kq + 4];
                a[mt][3] = As[s][m + 8][k + kq + 4];
            }
#pragma unroll
            for (int nt = 0; nt < 8; ++nt) {
                int n = warpN + nt * 8 + gm;
                b[nt][0] = Bs[s][n][k + kq];
                b[nt][1] = Bs[s][n][k + kq + 4];
            }
#pragma unroll
            for (int mt = 0; mt < 2; ++mt)
#pragma unroll
                for (int nt = 0; nt < 8; ++nt)
                    mma_tf32(acc[mt][nt], a[mt], b[nt]);
        }
        __syncthreads();
    }

    float* Cb = C + (size_t)batch * NS * N;
#pragma unroll
    for (int mt = 0; mt < 2; ++mt)
#pragma unroll
        for (int nt = 0; nt < 8; ++nt) {
            int r0 = iBase + warpM + mt * 16 + gm;
            int c0 = jBase + warpN + nt * 8 + kq * 2;
#pragma unroll
            for (int half = 0; half < 2; ++half)
                *(float2*)&Cb[(size_t)(r0 + half * 8) * N + c0] =
                    make_float2(acc[mt][nt][half * 2], acc[mt][nt][half * 2 + 1]);
        }
}

// ============================================================================
// flash_tf32: fused scores(QK^T + rel-pos bias) -> online softmax -> PV.
// Grid (8 iTiles, 64 batch-heads), 256 threads / 8 warps.
// Warp tile = 16 rows x FULL 128 cols  => softmax is quad-shfl only.
// Q fragments resident in registers; K/V staged with 2-stage cp.async.
// P is remapped from the S accumulator to A-fragments via quad shuffles.
// ============================================================================
__global__ __launch_bounds__(256, 1) void flash_tf32(
    const float* __restrict__ q, const float* __restrict__ k,
    const float* __restrict__ v,
    const float* __restrict__ c2p, const float* __restrict__ p2c,
    const int* __restrict__ tbl, float* __restrict__ ctx)
{
    __shared__ float Ks[2][128][20];   // K (and Q at start) staging
    __shared__ float Vs[2][16][72];    // V staging

    const int t = threadIdx.x, l = t & 31, w = t >> 5;
    const int gm = l >> 2, kq = l & 3;
    const int warpM = w * 16;
    const int z = blockIdx.y;
    const int bz = z >> 4, h = z & 15;
    const int iBase = blockIdx.x * 128;

    const float* Qb = q + (size_t)z * NS * HD;
    const float* Kb = k + (size_t)z * NS * HD;
    const float* Vb = v + (size_t)z * NS * HD;
    const float* c2pr = c2p + (size_t)z * NS * NK2;
    const float* p2cr = p2c + (size_t)z * NS * NK2;

    const int sr = t >> 1, scc = (t & 1) * 8;   // 128x16 staging
    const int vk = t >> 4, vc = (t & 15) * 4;   // 16x64 staging

    const int i0 = iBase + warpM + gm;
    const int i1 = i0 + 8;

    // ---- Q fragments -> registers (staged through Ks) ----
    float aq[8][4];
#pragma unroll
    for (int c = 0; c < 4; ++c) {
        int s = c & 1;
        cp16(&Ks[s][sr][scc],     Qb + (size_t)(iBase + sr) * HD + c * 16 + scc);
        cp16(&Ks[s][sr][scc + 4], Qb + (size_t)(iBase + sr) * HD + c * 16 + scc + 4);
        cp_commit(); cp_wait0();
        __syncthreads();
        int m = warpM + gm;
#pragma unroll
        for (int ks = 0; ks < 2; ++ks) {
            int kk = ks * 8;
            aq[c * 2 + ks][0] = Ks[s][m][kk + kq];
            aq[c * 2 + ks][1] = Ks[s][m + 8][kk + kq];
            aq[c * 2 + ks][2] = Ks[s][m][kk + kq + 4];
            aq[c * 2 + ks][3] = Ks[s][m + 8][kk + kq + 4];
        }
        __syncthreads();
    }

    float m0 = -INFINITY, m1 = -INFINITY, l0 = 0.f, l1 = 0.f;
    float o[8][4];
#pragma unroll
    for (int i = 0; i < 8; ++i)
#pragma unroll
        for (int e = 0; e < 4; ++e) o[i][e] = 0.f;

    const float inv192 = 0.07216878364870322f;  // 1/sqrt(64*3)
    const float inv128 = 0.08838834764831845f;  // 1/sqrt(64*2)

    for (int jt = 0; jt < 8; ++jt) {
        const int jBase = jt * 128;

        // ---- S = Q K^T for this j-tile ----
        float sc[16][4];
#pragma unroll
        for (int i = 0; i < 16; ++i)
#pragma unroll
            for (int e = 0; e < 4; ++e) sc[i][e] = 0.f;

        cp16(&Ks[0][sr][scc],     Kb + (size_t)(jBase + sr) * HD + scc);
        cp16(&Ks[0][sr][scc + 4], Kb + (size_t)(jBase + sr) * HD + scc + 4);
        cp_commit();
#pragma unroll
        for (int c = 0; c < 4; ++c) {
            if (c + 1 < 4) {
                int d0 = (c + 1) * 16, s = (c + 1) & 1;
                cp16(&Ks[s][sr][scc],     Kb + (size_t)(jBase + sr) * HD + d0 + scc);
                cp16(&Ks[s][sr][scc + 4], Kb + (size_t)(jBase + sr) * HD + d0 + scc + 4);
                cp_commit(); cp_wait1();
            } else {
                cp_wait0();
            }
            __syncthreads();
            const int s = c & 1;
#pragma unroll
            for (int ks = 0; ks < 2; ++ks) {
                const int kk = ks * 8;
#pragma unroll
                for (int nt = 0; nt < 16; ++nt) {
                    int n = nt * 8 + gm;
                    float b[2];
                    b[0] = Ks[s][n][kk + kq];
                    b[1] = Ks[s][n][kk + kq + 4];
                    mma_tf32(sc[nt], aq[c * 2 + ks], b);
                }
            }
            __syncthreads();
        }

        // ---- bias epilogue ----
#pragma unroll
        for (int nt = 0; nt < 16; ++nt) {
#pragma unroll
            for (int e = 0; e < 4; ++e) {
                int i = (e < 2) ? i0 : i1;
                int j = jBase + nt * 8 + kq * 2 + (e & 1);
                int delta = i - j;
                int t1 = tbl[delta + (NS - 1)];
                int idx1 = min(max(t1 + SPAN, 0), 2 * SPAN - 1);
                int t2 = tbl[(NS - 1) - delta];
                int idx2 = min(max(SPAN - t2, 0), 2 * SPAN - 1);
                float bias = c2pr[(size_t)i * NK2 + idx1] + p2cr[(size_t)j * NK2 + idx2];
                sc[nt][e] = sc[nt][e] * inv192 + bias * inv128;
            }
        }

        // ---- online softmax (quad shuffles; rows fully in-warp) ----
        float tm0 = -INFINITY, tm1 = -INFINITY;
#pragma unroll
        for (int nt = 0; nt < 16; ++nt) {
            tm0 = fmaxf(tm0, fmaxf(sc[nt][0], sc[nt][1]));
            tm1 = fmaxf(tm1, fmaxf(sc[nt][2], sc[nt][3]));
        }
        tm0 = fmaxf(tm0, __shfl_xor_sync(0xffffffffu, tm0, 1));
        tm0 = fmaxf(tm0, __shfl_xor_sync(0xffffffffu, tm0, 2));
        tm1 = fmaxf(tm1, __shfl_xor_sync(0xffffffffu, tm1, 1));
        tm1 = fmaxf(tm1, __shfl_xor_sync(0xffffffffu, tm1, 2));

        float mn0 = fmaxf(m0, tm0), mn1 = fmaxf(m1, tm1);
        float fac0 = expf(m0 - mn0), fac1 = expf(m1 - mn1);
        m0 = mn0; m1 = mn1;

        float s0 = 0.f, s1 = 0.f;
#pragma unroll
        for (int nt = 0; nt < 16; ++nt) {
            sc[nt][0] = f2tf(expf(sc[nt][0] - mn0));
            sc[nt][1] = f2tf(expf(sc[nt][1] - mn0));
            sc[nt][2] = f2tf(expf(sc[nt][2] - mn1));
            sc[nt][3] = f2tf(expf(sc[nt][3] - mn1));
            s0 += sc[nt][0] + sc[nt][1];
            s1 += sc[nt][2] + sc[nt][3];
        }
        s0 += __shfl_xor_sync(0xffffffffu, s0, 1);
        s0 += __shfl_xor_sync(0xffffffffu, s0, 2);
        s1 += __shfl_xor_sync(0xffffffffu, s1, 1);
        s1 += __shfl_xor_sync(0xffffffffu, s1, 2);
        l0 = l0 * fac0 + s0;
        l1 = l1 * fac1 + s1;

#pragma unroll
        for (int nt = 0; nt < 8; ++nt) {
            o[nt][0] *= fac0; o[nt][1] *= fac0;
            o[nt][2] *= fac1; o[nt][3] *= fac1;
        }

        // ---- PV: O += P @ V_tile ----
        cp16(&Vs[0][vk][vc], Vb + (size_t)(jBase + vk) * HD + vc);
        cp_commit();
        const int srcA = (l & ~3) | (kq >> 1);
        const int srcB = srcA + 2;
        const bool odd = (kq & 1);
#pragma unroll
        for (int c = 0; c < 8; ++c) {
            if (c + 1 < 8) {
                cp16(&Vs[(c + 1) & 1][vk][vc],
                     Vb + (size_t)(jBase + (c + 1) * 16 + vk) * HD + vc);
                cp_commit(); cp_wait1();
            } else {
                cp_wait0();
            }
            __syncthreads();
            const int s = c & 1;
#pragma unroll
            for (int ks2 = 0; ks2 < 2; ++ks2) {
                const int ksg = c * 2 + ks2;
                const int kk = ks2 * 8;
                float e0 = __shfl_sync(0xffffffffu, sc[ksg][0], srcA);
                float e1 = __shfl_sync(0xffffffffu, sc[ksg][1], srcA);
                float e2 = __shfl_sync(0xffffffffu, sc[ksg][2], srcA);
                float e3 = __shfl_sync(0xffffffffu, sc[ksg][3], srcA);
                float f0 = __shfl_sync(0xffffffffu, sc[ksg][0], srcB);
                float f1 = __shfl_sync(0xffffffffu, sc[ksg][1], srcB);
                float f2 = __shfl_sync(0xffffffffu, sc[ksg][2], srcB);
                float f3 = __shfl_sync(0xffffffffu, sc[ksg][3], srcB);
                float pa[4];
                pa[0] = odd ? e1 : e0;   // P[row gm][kk+kq]
                pa[1] = odd ? e3 : e2;   // P[row gm+8][kk+kq]
                pa[2] = odd ? f1 : f0;   // P[row gm][kk+kq+4]
                pa[3] = odd ? f3 : f2;   // P[row gm+8][kk+kq+4]
#pragma unroll
                for (int nt = 0; nt < 8; ++nt) {
                    int n = nt * 8 + gm;
                    float b[2];
                    b[0] = Vs[s][kk + kq][n];
                    b[1] = Vs[s][kk + kq + 4][n];
                    mma_tf32(o[nt], pa, b);
                }
            }
            __syncthreads();
        }
    }

    // ---- normalize and store ctx ----
    float r0 = 1.0f / l0, r1 = 1.0f / l1;
#pragma unroll
    for (int nt = 0; nt < 8; ++nt) {
        int c0 = nt * 8 + kq * 2;
        *(float2*)&ctx[((size_t)bz * NS + i0) * ND + h * HD + c0] =
            make_float2(o[nt][0] * r0, o[nt][1] * r0);
        *(float2*)&ctx[((size_t)bz * NS + i1) * ND + h * HD + c0] =
            make_float2(o[nt][2] * r1, o[nt][3] * r1);
    }
}

// ---------------- launch ----------------
extern "C" void kernel_launch(void* const* d_in, const int* in_sizes, int n_in,
                              void* d_out, int out_size) {
    const float* hs    = (const float*)d_in[0];
    const float* Wq    = (const float*)d_in[1];
    const float* bq    = (const float*)d_in[2];
    const float* Wk    = (const float*)d_in[3];
    const float* bk    = (const float*)d_in[4];
    const float* Wv    = (const float*)d_in[5];
    const float* bv    = (const float*)d_in[6];
    const float* Wo    = (const float*)d_in[7];
    const float* bo    = (const float*)d_in[8];
    const float* rel   = (const float*)d_in[9];
    const float* ln_g  = (const float*)d_in[10];
    const float* ln_b  = (const float*)d_in[11];
    const float* Wpk   = (const float*)d_in[12];
    const float* bpk   = (const float*)d_in[13];
    const float* Wpq   = (const float*)d_in[14];
    const float* bpq   = (const float*)d_in[15];
    float* out = (float*)d_out;

    float *p_re, *p_q, *p_k, *p_v, *p_posk, *p_posq, *p_c2p, *p_p2c, *p_ctx;
    int* p_tbl;
    cudaGetSymbolAddress((void**)&p_re, g_re);
    cudaGetSymbolAddress((void**)&p_q, g_q);
    cudaGetSymbolAddress((void**)&p_k, g_k);
    cudaGetSymbolAddress((void**)&p_v, g_v);
    cudaGetSymbolAddress((void**)&p_posk, g_posk);
    cudaGetSymbolAddress((void**)&p_posq, g_posq);
    cudaGetSymbolAddress((void**)&p_c2p, g_c2p);
    cudaGetSymbolAddress((void**)&p_p2c, g_p2c);
    cudaGetSymbolAddress((void**)&p_ctx, g_ctx);
    cudaGetSymbolAddress((void**)&p_tbl, g_tbl);

    build_tbl_kernel<<<9, 256>>>(p_tbl);
    ln_kernel<<<NK2, 256>>>(rel, ln_g, ln_b, p_re);

    // merged Q/K/V projections -> [B,H,S,hd] (tf32-rounded stores)
    mm_bias_tf32<<<dim3(8, 32, 3), 256>>>(hs, Wq, Wk, Wv, bq, bk, bv,
                                          p_q, p_k, p_v, NB * NS, ND, ND, NS);

    // merged positional projections -> [H,2K,hd]
    mm_bias_tf32<<<dim3(8, 4, 2), 256>>>(p_re, Wpk, Wpq, Wpq, bpk, bpq, bpq,
                                         p_posk, p_posq, p_posq, NK2, ND, ND, NK2);

    // c2p / p2c
    nt64_tf32<<<dim3(4, 8, 64), 256>>>(p_q, p_posk, p_c2p, NK2, NH);
    nt64_tf32<<<dim3(4, 8, 64), 256>>>(p_k, p_posq, p_p2c, NK2, NH);

    // fused attention: scores + bias + softmax + PV -> ctx
    flash_tf32<<<dim3(8, 64), 256>>>(p_q, p_k, p_v, p_c2p, p_p2c, p_tbl, p_ctx);

    // out = ctx @ Wo + bo
    mm_bias_tf32<<<dim3(8, 32, 1), 256>>>(p_ctx, Wo, Wo, Wo, bo, bo, bo,
                                          out, out, out, NB * NS, ND, ND, 0);
}

// round 7
// speedup vs baseline: 3.2567x; 1.0430x over previous
#include <cuda_runtime.h>
#include <math.h>

// Shapes (fixed by the problem)
#define NB 4
#define NH 16
#define NS 1024
#define ND 1024
#define HD 64
#define NK2 512   // 2 * BUCKETS
#define SPAN 256  // BUCKETS

// ---------------- scratch (device globals; no allocs allowed) ----------------
__device__ float g_re[NK2 * ND];
__device__ float g_q[(size_t)NB * NH * NS * HD];
__device__ float g_k[(size_t)NB * NH * NS * HD];
__device__ float g_v[(size_t)NB * NH * NS * HD];
__device__ float g_posk[NH * NK2 * HD];
__device__ float g_posq[NH * NK2 * HD];
__device__ float g_c2p[(size_t)NB * NH * NS * NK2];
__device__ float g_p2c[(size_t)NB * NH * NS * NK2];
__device__ float g_ctx[(size_t)NB * NS * ND];
__device__ int   g_tbl[2 * NS - 1];

// ---------------- helpers ----------------
__device__ __forceinline__ float f2tf(float x) {
    unsigned u;
    asm("cvt.rna.tf32.f32 %0, %1;" : "=r"(u) : "f"(x));
    return __uint_as_float(u);
}

__device__ __forceinline__ void mma_tf32(float* c, const float* a, const float* b) {
    asm volatile("mma.sync.aligned.m16n8k8.row.col.f32.tf32.tf32.f32 "
                 "{%0,%1,%2,%3}, {%4,%5,%6,%7}, {%8,%9}, {%0,%1,%2,%3};\n"
                 : "+f"(c[0]), "+f"(c[1]), "+f"(c[2]), "+f"(c[3])
                 : "r"(__float_as_uint(a[0])), "r"(__float_as_uint(a[1])),
                   "r"(__float_as_uint(a[2])), "r"(__float_as_uint(a[3])),
                   "r"(__float_as_uint(b[0])), "r"(__float_as_uint(b[1])));
}

__device__ __forceinline__ void cp16(float* dst, const float* src) {
    unsigned s = (unsigned)__cvta_generic_to_shared(dst);
    asm volatile("cp.async.cg.shared.global [%0], [%1], 16;" :: "r"(s), "l"(src));
}
__device__ __forceinline__ void cp_commit() { asm volatile("cp.async.commit_group;"); }
__device__ __forceinline__ void cp_wait0()  { asm volatile("cp.async.wait_group 0;"); }
__device__ __forceinline__ void cp_wait1()  { asm volatile("cp.async.wait_group 1;"); }

// ---------------- bucket table ----------------
__global__ void build_tbl_kernel(int* tbl) {
    int i = blockIdx.x * blockDim.x + threadIdx.x;
    if (i >= 2 * NS - 1) return;
    int rel = i - (NS - 1);
    const float mid = 128.0f;
    float signf = (rel > 0) ? 1.0f : (rel < 0 ? -1.0f : 0.0f);
    float abs_pos = (rel < 128 && rel > -128) ? 127.0f : fabsf((float)rel);
    float bucket;
    if (abs_pos <= mid) {
        bucket = (float)rel;
    } else {
        const float LOGC = 1.3843393289f;  // log(511/128) as f32
        float log_pos = ceilf(logf(abs_pos / mid) / LOGC * 127.0f) + mid;
        bucket = log_pos * signf;
    }
    tbl[i] = (int)bucket;
}

// ---------------- LayerNorm for rel_emb [512,1024] ----------------
__global__ void ln_kernel(const float* __restrict__ x, const float* __restrict__ g,
                          const float* __restrict__ b, float* __restrict__ y) {
    int row = blockIdx.x;
    const float* xr = x + (size_t)row * ND;
    __shared__ float red[256];
    int tid = threadIdx.x;

    float s = 0.f;
    for (int i = tid; i < ND; i += 256) s += xr[i];
    red[tid] = s; __syncthreads();
    for (int o = 128; o > 0; o >>= 1) { if (tid < o) red[tid] += red[tid + o]; __syncthreads(); }
    float mu = red[0] * (1.0f / ND);
    __syncthreads();

    float v = 0.f;
    for (int i = tid; i < ND; i += 256) { float d = xr[i] - mu; v += d * d; }
    red[tid] = v; __syncthreads();
    for (int o = 128; o > 0; o >>= 1) { if (tid < o) red[tid] += red[tid + o]; __syncthreads(); }
    float var = red[0] * (1.0f / ND);
    float inv = 1.0f / sqrtf(var + 1e-5f);

    for (int i = tid; i < ND; i += 256)
        y[(size_t)row * ND + i] = (xr[i] - mu) * inv * g[i] + b[i];
}

// ============================================================================
// mm_jobs_tf32: up to 5 independent GEMMs C = A[M,1024] @ W[1024,1024] + bias
// in one launch (blockIdx.z picks the job; oversized y-tiles early-exit).
// 128x128 tile, K-chunk 16, 2-stage cp.async, 2 CTAs/SM.
// ============================================================================
struct MMJob {
    const float* A; const float* W; const float* bias; float* C;
    int M; int splitR;   // splitR==0: row-major out; else head-split (+tf32 round)
};
struct MMJobs { MMJob j[5]; };

__global__ __launch_bounds__(256, 2) void mm_jobs_tf32(MMJobs jobs)
{
    __shared__ float As[2][128][20];
    __shared__ float Bs[2][16][136];

    const MMJob jb = jobs.j[blockIdx.z];
    if (blockIdx.y * 128 >= jb.M) return;
    const float* A = jb.A; const float* W = jb.W;
    const float* bias = jb.bias; float* C = jb.C;
    const int splitR = jb.splitR;

    const int t = threadIdx.x, l = t & 31, w = t >> 5;
    const int gm = l >> 2, kq = l & 3;
    const int warpM = (w >> 1) * 32, warpN = (w & 1) * 64;
    const int rowBase = blockIdx.y * 128, colBase = blockIdx.x * 128;

    float acc[2][8][4];
#pragma unroll
    for (int i = 0; i < 2; ++i)
#pragma unroll
        for (int j = 0; j < 8; ++j)
#pragma unroll
            for (int e = 0; e < 4; ++e) acc[i][j][e] = 0.f;

    const int ar = t >> 1, ac = (t & 1) * 8;
    const int bk = t >> 4, bc = (t & 15) * 8;

    cp16(&As[0][ar][ac],     A + (size_t)(rowBase + ar) * ND + ac);
    cp16(&As[0][ar][ac + 4], A + (size_t)(rowBase + ar) * ND + ac + 4);
    cp16(&Bs[0][bk][bc],     W + (size_t)bk * ND + colBase + bc);
    cp16(&Bs[0][bk][bc + 4], W + (size_t)bk * ND + colBase + bc + 4);
    cp_commit();

    for (int c = 0; c < ND / 16; ++c) {
        if (c + 1 < ND / 16) {
            int k0 = (c + 1) * 16, s = (c + 1) & 1;
            cp16(&As[s][ar][ac],     A + (size_t)(rowBase + ar) * ND + k0 + ac);
            cp16(&As[s][ar][ac + 4], A + (size_t)(rowBase + ar) * ND + k0 + ac + 4);
            cp16(&Bs[s][bk][bc],     W + (size_t)(k0 + bk) * ND + colBase + bc);
            cp16(&Bs[s][bk][bc + 4], W + (size_t)(k0 + bk) * ND + colBase + bc + 4);
            cp_commit();
            cp_wait1();
        } else {
            cp_wait0();
        }
        __syncthreads();

        const int s = c & 1;
#pragma unroll
        for (int ks = 0; ks < 2; ++ks) {
            const int k = ks * 8;
            float a[2][4], b[8][2];
#pragma unroll
            for (int mt = 0; mt < 2; ++mt) {
                int m = warpM + mt * 16 + gm;
                a[mt][0] = f2tf(As[s][m][k + kq]);
                a[mt][1] = f2tf(As[s][m + 8][k + kq]);
                a[mt][2] = f2tf(As[s][m][k + kq + 4]);
                a[mt][3] = f2tf(As[s][m + 8][k + kq + 4]);
            }
#pragma unroll
            for (int nt = 0; nt < 8; ++nt) {
                int n = warpN + nt * 8 + gm;
                b[nt][0] = f2tf(Bs[s][k + kq][n]);
                b[nt][1] = f2tf(Bs[s][k + kq + 4][n]);
            }
#pragma unroll
            for (int mt = 0; mt < 2; ++mt)
#pragma unroll
                for (int nt = 0; nt < 8; ++nt)
                    mma_tf32(acc[mt][nt], a[mt], b[nt]);
        }
        __syncthreads();
    }

#pragma unroll
    for (int mt = 0; mt < 2; ++mt) {
#pragma unroll
        for (int nt = 0; nt < 8; ++nt) {
            int r0 = rowBase + warpM + mt * 16 + gm;
            int c0 = colBase + warpN + nt * 8 + kq * 2;
#pragma unroll
            for (int half = 0; half < 2; ++half) {
                int r = r0 + half * 8;
                float v0 = acc[mt][nt][half * 2 + 0] + bias[c0];
                float v1 = acc[mt][nt][half * 2 + 1] + bias[c0 + 1];
                if (splitR == 0) {
                    *(float2*)&C[(size_t)r * ND + c0] = make_float2(v0, v1);
                } else {
                    v0 = f2tf(v0); v1 = f2tf(v1);
                    int h = c0 >> 6, d = c0 & 63;
                    int bb = r / splitR, rr = r - bb * splitR;
                    *(float2*)&C[(((size_t)bb * NH + h) * splitR + rr) * HD + d] =
                        make_float2(v0, v1);
                }
            }
        }
    }
}

// ============================================================================
// nt64_pair_tf32: c2p and p2c in one launch.
// z<64:  C2P[z][i][kk] = q[z] . posk[z%16]
// z>=64: P2C[z-64][i][kk] = k[z-64] . posq[(z-64)%16]
// ============================================================================
__global__ __launch_bounds__(256, 2) void nt64_pair_tf32(
    const float* __restrict__ q, const float* __restrict__ posk,
    const float* __restrict__ kk, const float* __restrict__ posq,
    float* __restrict__ c2p, float* __restrict__ p2c)
{
    __shared__ float As[2][128][20];
    __shared__ float Bs[2][128][20];

    const int t = threadIdx.x, l = t & 31, w = t >> 5;
    const int gm = l >> 2, kq = l & 3;
    const int warpM = (w >> 1) * 32, warpN = (w & 1) * 64;
    const int zz = blockIdx.z;
    const int batch = zz & 63;
    const int iBase = blockIdx.y * 128, jBase = blockIdx.x * 128;

    const float* Ab = ((zz < 64) ? q : kk) + (size_t)batch * NS * HD;
    const float* Bb = ((zz < 64) ? posk : posq) + (size_t)(batch & 15) * NK2 * HD;
    float* Cb = ((zz < 64) ? c2p : p2c) + (size_t)batch * NS * NK2;

    float acc[2][8][4];
#pragma unroll
    for (int i = 0; i < 2; ++i)
#pragma unroll
        for (int j = 0; j < 8; ++j)
#pragma unroll
            for (int e = 0; e < 4; ++e) acc[i][j][e] = 0.f;

    const int sr = t >> 1, sc = (t & 1) * 8;

    cp16(&As[0][sr][sc],     Ab + (size_t)(iBase + sr) * HD + sc);
    cp16(&As[0][sr][sc + 4], Ab + (size_t)(iBase + sr) * HD + sc + 4);
    cp16(&Bs[0][sr][sc],     Bb + (size_t)(jBase + sr) * HD + sc);
    cp16(&Bs[0][sr][sc + 4], Bb + (size_t)(jBase + sr) * HD + sc + 4);
    cp_commit();

#pragma unroll
    for (int c = 0; c < 4; ++c) {
        if (c + 1 < 4) {
            int d0 = (c + 1) * 16, s = (c + 1) & 1;
            cp16(&As[s][sr][sc],     Ab + (size_t)(iBase + sr) * HD + d0 + sc);
            cp16(&As[s][sr][sc + 4], Ab + (size_t)(iBase + sr) * HD + d0 + sc + 4);
            cp16(&Bs[s][sr][sc],     Bb + (size_t)(jBase + sr) * HD + d0 + sc);
            cp16(&Bs[s][sr][sc + 4], Bb + (size_t)(jBase + sr) * HD + d0 + sc + 4);
            cp_commit();
            cp_wait1();
        } else {
            cp_wait0();
        }
        __syncthreads();

        const int s = c & 1;
#pragma unroll
        for (int ks = 0; ks < 2; ++ks) {
            const int k = ks * 8;
            float a[2][4], b[8][2];
#pragma unroll
            for (int mt = 0; mt < 2; ++mt) {
                int m = warpM + mt * 16 + gm;
                a[mt][0] = As[s][m][k + kq];
                a[mt][1] = As[s][m + 8][k + kq];
                a[mt][2] = As[s][m][k + kq + 4];
                a[mt][3] = As[s][m + 8][k + kq + 4];
            }
#pragma unroll
            for (int nt = 0; nt < 8; ++nt) {
                int n = warpN + nt * 8 + gm;
                b[nt][0] = Bs[s][n][k + kq];
                b[nt][1] = Bs[s][n][k + kq + 4];
            }
#pragma unroll
            for (int mt = 0; mt < 2; ++mt)
#pragma unroll
                for (int nt = 0; nt < 8; ++nt)
                    mma_tf32(acc[mt][nt], a[mt], b[nt]);
        }
        __syncthreads();
    }

#pragma unroll
    for (int mt = 0; mt < 2; ++mt)
#pragma unroll
        for (int nt = 0; nt < 8; ++nt) {
            int r0 = iBase + warpM + mt * 16 + gm;
            int c0 = jBase + warpN + nt * 8 + kq * 2;
#pragma unroll
            for (int half = 0; half < 2; ++half)
                *(float2*)&Cb[(size_t)(r0 + half * 8) * NK2 + c0] =
                    make_float2(acc[mt][nt][half * 2], acc[mt][nt][half * 2 + 1]);
        }
}

// ============================================================================
// flash_tf32: fused scores(QK^T + rel-pos bias) -> online softmax -> PV.
// Whole-tile staging: X0 holds the full K (or Q) tile, X1 the full V tile.
// 3 __syncthreads per j-tile; 128 MMAs between barriers.
// Dynamic smem: 2 * 128 * 72 * 4 = 73728 bytes.
// ============================================================================
__global__ __launch_bounds__(256, 1) void flash_tf32(
    const float* __restrict__ q, const float* __restrict__ k,
    const float* __restrict__ v,
    const float* __restrict__ c2p, const float* __restrict__ p2c,
    const int* __restrict__ tbl, float* __restrict__ ctx)
{
    extern __shared__ float smf[];
    float (*X0)[72] = (float(*)[72])smf;              // K tile (Q at start)
    float (*X1)[72] = (float(*)[72])(smf + 128 * 72); // V tile

    const int t = threadIdx.x, l = t & 31, w = t >> 5;
    const int gm = l >> 2, kq = l & 3;
    const int warpM = w * 16;
    const int z = blockIdx.y;
    const int bz = z >> 4, h = z & 15;
    const int iBase = blockIdx.x * 128;

    const float* Qb = q + (size_t)z * NS * HD;
    const float* Kb = k + (size_t)z * NS * HD;
    const float* Vb = v + (size_t)z * NS * HD;
    const float* c2pr = c2p + (size_t)z * NS * NK2;
    const float* p2cr = p2c + (size_t)z * NS * NK2;

    const int sr = t >> 1, cb = (t & 1) * 32;  // 2 thr/row, 32 cols each
    const int i0 = iBase + warpM + gm;
    const int i1 = i0 + 8;

    // ---- load Q tile -> X0, extract fragments ----
#pragma unroll
    for (int i = 0; i < 8; ++i)
        cp16(&X0[sr][cb + i * 4], Qb + (size_t)(iBase + sr) * HD + cb + i * 4);
    cp_commit(); cp_wait0();
    __syncthreads();

    float aq[8][4];
    {
        int m = warpM + gm;
#pragma unroll
        for (int ks = 0; ks < 8; ++ks) {
            int kk = ks * 8;
            aq[ks][0] = X0[m][kk + kq];
            aq[ks][1] = X0[m + 8][kk + kq];
            aq[ks][2] = X0[m][kk + kq + 4];
            aq[ks][3] = X0[m + 8][kk + kq + 4];
        }
    }
    __syncthreads();

    // prefetch K(0) -> X0
#pragma unroll
    for (int i = 0; i < 8; ++i)
        cp16(&X0[sr][cb + i * 4], Kb + (size_t)sr * HD + cb + i * 4);
    cp_commit();   // pending: [K0]

    float m0 = -INFINITY, m1 = -INFINITY, l0 = 0.f, l1 = 0.f;
    float o[8][4];
#pragma unroll
    for (int i = 0; i < 8; ++i)
#pragma unroll
        for (int e = 0; e < 4; ++e) o[i][e] = 0.f;

    const float inv192 = 0.07216878364870322f;  // 1/sqrt(64*3)
    const float inv128 = 0.08838834764831845f;  // 1/sqrt(64*2)
    const int srcA = (l & ~3) | (kq >> 1);
    const int srcB = srcA + 2;
    const bool odd = (kq & 1);

    for (int jt = 0; jt < 8; ++jt) {
        const int jBase = jt * 128;

        // issue V(jt) -> X1 ; then wait for K(jt)
#pragma unroll
        for (int i = 0; i < 8; ++i)
            cp16(&X1[sr][cb + i * 4], Vb + (size_t)(jBase + sr) * HD + cb + i * 4);
        cp_commit();        // pending: [K(jt), V(jt)]
        cp_wait1();         // K(jt) done
        __syncthreads();

        // ---- S = Q K^T (128 MMAs, no barriers) ----
        float sc[16][4];
#pragma unroll
        for (int i = 0; i < 16; ++i)
#pragma unroll
            for (int e = 0; e < 4; ++e) sc[i][e] = 0.f;
#pragma unroll
        for (int ks = 0; ks < 8; ++ks) {
            const int kk = ks * 8;
#pragma unroll
            for (int nt = 0; nt < 16; ++nt) {
                int n = nt * 8 + gm;
                float b[2];
                b[0] = X0[n][kk + kq];
                b[1] = X0[n][kk + kq + 4];
                mma_tf32(sc[nt], aq[ks], b);
            }
        }
        __syncthreads();    // all warps done reading X0

        // prefetch K(jt+1) -> X0 (overlaps softmax)
        if (jt + 1 < 8) {
#pragma unroll
            for (int i = 0; i < 8; ++i)
                cp16(&X0[sr][cb + i * 4],
                     Kb + (size_t)((jt + 1) * 128 + sr) * HD + cb + i * 4);
            cp_commit();    // pending: [V(jt), K(jt+1)]
        }

        // ---- bias epilogue ----
#pragma unroll
        for (int nt = 0; nt < 16; ++nt) {
#pragma unroll
            for (int e = 0; e < 4; ++e) {
                int i = (e < 2) ? i0 : i1;
                int j = jBase + nt * 8 + kq * 2 + (e & 1);
                int delta = i - j;
                int t1 = tbl[delta + (NS - 1)];
                int idx1 = min(max(t1 + SPAN, 0), 2 * SPAN - 1);
                int t2 = tbl[(NS - 1) - delta];
                int idx2 = min(max(SPAN - t2, 0), 2 * SPAN - 1);
                float bias = c2pr[(size_t)i * NK2 + idx1] + p2cr[(size_t)j * NK2 + idx2];
                sc[nt][e] = sc[nt][e] * inv192 + bias * inv128;
            }
        }

        // ---- online softmax (quad shuffles) ----
        float tm0 = -INFINITY, tm1 = -INFINITY;
#pragma unroll
        for (int nt = 0; nt < 16; ++nt) {
            tm0 = fmaxf(tm0, fmaxf(sc[nt][0], sc[nt][1]));
            tm1 = fmaxf(tm1, fmaxf(sc[nt][2], sc[nt][3]));
        }
        tm0 = fmaxf(tm0, __shfl_xor_sync(0xffffffffu, tm0, 1));
        tm0 = fmaxf(tm0, __shfl_xor_sync(0xffffffffu, tm0, 2));
        tm1 = fmaxf(tm1, __shfl_xor_sync(0xffffffffu, tm1, 1));
        tm1 = fmaxf(tm1, __shfl_xor_sync(0xffffffffu, tm1, 2));

        float mn0 = fmaxf(m0, tm0), mn1 = fmaxf(m1, tm1);
        float fac0 = expf(m0 - mn0), fac1 = expf(m1 - mn1);
        m0 = mn0; m1 = mn1;

        float s0 = 0.f, s1 = 0.f;
#pragma unroll
        for (int nt = 0; nt < 16; ++nt) {
            sc[nt][0] = f2tf(expf(sc[nt][0] - mn0));
            sc[nt][1] = f2tf(expf(sc[nt][1] - mn0));
            sc[nt][2] = f2tf(expf(sc[nt][2] - mn1));
            sc[nt][3] = f2tf(expf(sc[nt][3] - mn1));
            s0 += sc[nt][0] + sc[nt][1];
            s1 += sc[nt][2] + sc[nt][3];
        }
        s0 += __shfl_xor_sync(0xffffffffu, s0, 1);
        s0 += __shfl_xor_sync(0xffffffffu, s0, 2);
        s1 += __shfl_xor_sync(0xffffffffu, s1, 1);
        s1 += __shfl_xor_sync(0xffffffffu, s1, 2);
        l0 = l0 * fac0 + s0;
        l1 = l1 * fac1 + s1;

#pragma unroll
        for (int nt = 0; nt < 8; ++nt) {
            o[nt][0] *= fac0; o[nt][1] *= fac0;
            o[nt][2] *= fac1; o[nt][3] *= fac1;
        }

        // ---- wait V(jt), then PV (128 MMAs, no barriers) ----
        if (jt + 1 < 8) cp_wait1(); else cp_wait0();
        __syncthreads();

#pragma unroll
        for (int ksg = 0; ksg < 16; ++ksg) {
            float e0 = __shfl_sync(0xffffffffu, sc[ksg][0], srcA);
            float e1 = __shfl_sync(0xffffffffu, sc[ksg][1], srcA);
            float e2 = __shfl_sync(0xffffffffu, sc[ksg][2], srcA);
            float e3 = __shfl_sync(0xffffffffu, sc[ksg][3], srcA);
            float f0 = __shfl_sync(0xffffffffu, sc[ksg][0], srcB);
            float f1 = __shfl_sync(0xffffffffu, sc[ksg][1], srcB);
            float f2 = __shfl_sync(0xffffffffu, sc[ksg][2], srcB);
            float f3 = __shfl_sync(0xffffffffu, sc[ksg][3], srcB);
            float pa[4];
            pa[0] = odd ? e1 : e0;
            pa[1] = odd ? e3 : e2;
            pa[2] = odd ? f1 : f0;
            pa[3] = odd ? f3 : f2;
#pragma unroll
            for (int nt = 0; nt < 8; ++nt) {
                int n = nt * 8 + gm;
                float b[2];
                b[0] = X1[ksg * 8 + kq][n];
                b[1] = X1[ksg * 8 + kq + 4][n];
                mma_tf32(o[nt], pa, b);
            }
        }
        __syncthreads();    // done reading X1 before next V issue
    }

    // ---- normalize and store ctx ----
    float r0 = 1.0f / l0, r1 = 1.0f / l1;
#pragma unroll
    for (int nt = 0; nt < 8; ++nt) {
        int c0 = nt * 8 + kq * 2;
        *(float2*)&ctx[((size_t)bz * NS + i0) * ND + h * HD + c0] =
            make_float2(o[nt][0] * r0, o[nt][1] * r0);
        *(float2*)&ctx[((size_t)bz * NS + i1) * ND + h * HD + c0] =
            make_float2(o[nt][2] * r1, o[nt][3] * r1);
    }
}

// ---------------- launch ----------------
extern "C" void kernel_launch(void* const* d_in, const int* in_sizes, int n_in,
                              void* d_out, int out_size) {
    const float* hs    = (const float*)d_in[0];
    const float* Wq    = (const float*)d_in[1];
    const float* bq    = (const float*)d_in[2];
    const float* Wk    = (const float*)d_in[3];
    const float* bk    = (const float*)d_in[4];
    const float* Wv    = (const float*)d_in[5];
    const float* bv    = (const float*)d_in[6];
    const float* Wo    = (const float*)d_in[7];
    const float* bo    = (const float*)d_in[8];
    const float* rel   = (const float*)d_in[9];
    const float* ln_g  = (const float*)d_in[10];
    const float* ln_b  = (const float*)d_in[11];
    const float* Wpk   = (const float*)d_in[12];
    const float* bpk   = (const float*)d_in[13];
    const float* Wpq   = (const float*)d_in[14];
    const float* bpq   = (const float*)d_in[15];
    float* out = (float*)d_out;

    float *p_re, *p_q, *p_k, *p_v, *p_posk, *p_posq, *p_c2p, *p_p2c, *p_ctx;
    int* p_tbl;
    cudaGetSymbolAddress((void**)&p_re, g_re);
    cudaGetSymbolAddress((void**)&p_q, g_q);
    cudaGetSymbolAddress((void**)&p_k, g_k);
    cudaGetSymbolAddress((void**)&p_v, g_v);
    cudaGetSymbolAddress((void**)&p_posk, g_posk);
    cudaGetSymbolAddress((void**)&p_posq, g_posq);
    cudaGetSymbolAddress((void**)&p_c2p, g_c2p);
    cudaGetSymbolAddress((void**)&p_p2c, g_p2c);
    cudaGetSymbolAddress((void**)&p_ctx, g_ctx);
    cudaGetSymbolAddress((void**)&p_tbl, g_tbl);

    static bool attr_done = false;
    if (!attr_done) {
        cudaFuncSetAttribute(flash_tf32,
                             cudaFuncAttributeMaxDynamicSharedMemorySize, 73728);
        attr_done = true;
    }

    build_tbl_kernel<<<9, 256>>>(p_tbl);
    ln_kernel<<<NK2, 256>>>(rel, ln_g, ln_b, p_re);

    // merged Q/K/V + pos-k/pos-q projections in one launch
    MMJobs jobs;
    jobs.j[0] = { hs,   Wq,  bq,  p_q,    NB * NS, NS  };
    jobs.j[1] = { hs,   Wk,  bk,  p_k,    NB * NS, NS  };
    jobs.j[2] = { hs,   Wv,  bv,  p_v,    NB * NS, NS  };
    jobs.j[3] = { p_re, Wpk, bpk, p_posk, NK2,     NK2 };
    jobs.j[4] = { p_re, Wpq, bpq, p_posq, NK2,     NK2 };
    mm_jobs_tf32<<<dim3(8, 32, 5), 256>>>(jobs);

    // c2p and p2c in one launch
    nt64_pair_tf32<<<dim3(4, 8, 128), 256>>>(p_q, p_posk, p_k, p_posq, p_c2p, p_p2c);

    // fused attention
    flash_tf32<<<dim3(8, 64), 256, 73728>>>(p_q, p_k, p_v, p_c2p, p_p2c, p_tbl, p_ctx);

    // out = ctx @ Wo + bo
    MMJobs jo;
    jo.j[0] = { p_ctx, Wo, bo, out, NB * NS, 0 };
    jo.j[1] = jo.j[0]; jo.j[2] = jo.j[0]; jo.j[3] = jo.j[0]; jo.j[4] = jo.j[0];
    mm_jobs_tf32<<<dim3(8, 32, 1), 256>>>(jo);
}